// round 2
// baseline (speedup 1.0000x reference)
#include <cuda_runtime.h>
#include <cstdint>

// Problem capacities (from reference setup_inputs)
#define N_MAX 50000
#define E_MAX 1600000
#define HW_MAX (N_MAX * 256)

// Scratch (device globals; no allocations allowed)
__device__ float g_h1[N_MAX * 256];
__device__ float g_h2[N_MAX * 64];
__device__ float g_hw[HW_MAX];
__device__ float g_w[E_MAX];
__device__ float g_inv[N_MAX];
__device__ float g_rowsum[N_MAX];
__device__ float g_deg[N_MAX];
__device__ float g_degG[N_MAX];
__device__ float g_sw[N_MAX];
__device__ float g_dinv[N_MAX];

// ---------------------------------------------------------------------------
// zero accumulators
__global__ void clear_kernel(float* a, float* b, float* c, int n) {
    int i = blockIdx.x * blockDim.x + threadIdx.x;
    if (i < n) { a[i] = 0.f; b[i] = 0.f; c[i] = 0.f; }
}

// per-node inverse L2 norm (zero rows -> 1)
__global__ void norm_kernel(const float* __restrict__ h, float* __restrict__ inv,
                            int n, int d) {
    int warp = (blockIdx.x * blockDim.x + threadIdx.x) >> 5;
    int lane = threadIdx.x & 31;
    if (warp >= n) return;
    const float* row = h + (size_t)warp * d;
    float acc = 0.f;
    for (int k = lane; k < d; k += 32) { float v = row[k]; acc += v * v; }
    #pragma unroll
    for (int o = 16; o; o >>= 1) acc += __shfl_xor_sync(0xffffffffu, acc, o);
    if (lane == 0) inv[warp] = (acc == 0.f) ? 1.f : 1.f / sqrtf(acc);
}

// per-edge cosine sim + threshold + rowsum accumulation
__global__ void sim_kernel(const float* __restrict__ h,
                           const int* __restrict__ ei,
                           const float* __restrict__ inv,
                           float* __restrict__ w, float* __restrict__ rowsum,
                           int E, int d) {
    int warp = (int)(((size_t)blockIdx.x * blockDim.x + threadIdx.x) >> 5);
    int lane = threadIdx.x & 31;
    if (warp >= E) return;
    int s = ei[warp];
    int t = ei[(size_t)E + warp];
    const float* hs = h + (size_t)s * d;
    const float* ht = h + (size_t)t * d;
    float acc = 0.f;
    for (int k = lane; k < d; k += 32) acc += hs[k] * ht[k];
    #pragma unroll
    for (int o = 16; o; o >>= 1) acc += __shfl_xor_sync(0xffffffffu, acc, o);
    if (lane == 0) {
        float sim = acc * inv[s] * inv[t];
        float wv = (s != t && sim >= 0.f) ? sim : 0.f;
        w[warp] = wv;
        if (wv > 0.f) atomicAdd(&rowsum[s], wv);
    }
}

// per-edge: L1 normalize, exp, deg count, GCN degree accumulation
__global__ void edge2_kernel(const int* __restrict__ ei,
                             float* __restrict__ w,
                             const float* __restrict__ rowsum,
                             float* __restrict__ deg, float* __restrict__ degG,
                             int E) {
    int e = blockIdx.x * blockDim.x + threadIdx.x;
    if (e >= E) return;
    float wv = w[e];
    float ew = 0.f;
    if (wv > 0.f) {
        int s = ei[e];
        float wn = wv / rowsum[s];
        ew = expf(wn);
        atomicAdd(&deg[s], 1.0f);
        int t = ei[(size_t)E + e];
        atomicAdd(&degG[t], ew);
    }
    w[e] = ew;
}

// per-node: self-loop weight + symmetric-norm inverse sqrt degree
__global__ void node2_kernel(const float* __restrict__ deg,
                             const float* __restrict__ degG,
                             float* __restrict__ sw, float* __restrict__ dinv,
                             int n) {
    int i = blockIdx.x * blockDim.x + threadIdx.x;
    if (i >= n) return;
    float s = expf(1.0f / (deg[i] + 1.0f));
    sw[i] = s;
    dinv[i] = 1.0f / sqrtf(degG[i] + s);
}

// ---------------------------------------------------------------------------
// Tiled fp32 GEMM: C[n x m] = A[n x k] * W[k x m]   (k multiple of 16)
#define BM 64
#define BN 64
#define BK 16
__global__ void gemm_kernel(const float* __restrict__ A,
                            const float* __restrict__ W,
                            float* __restrict__ C, int n, int k, int m) {
    __shared__ float As[BK][BM];
    __shared__ float Ws[BK][BN];
    int bm = blockIdx.y * BM;
    int bn = blockIdx.x * BN;
    int tid = threadIdx.x;
    int tr = tid >> 4, tc = tid & 15;
    float acc[4][4] = {};
    for (int k0 = 0; k0 < k; k0 += BK) {
        #pragma unroll
        for (int i = tid; i < BM * BK; i += 256) {
            int r = i >> 4, c = i & 15;
            int gr = bm + r;
            As[c][r] = (gr < n) ? A[(size_t)gr * k + k0 + c] : 0.f;
        }
        #pragma unroll
        for (int i = tid; i < BK * BN; i += 256) {
            int r = i >> 6, c = i & 63;
            int gc = bn + c;
            Ws[r][c] = (gc < m) ? W[(size_t)(k0 + r) * m + gc] : 0.f;
        }
        __syncthreads();
        #pragma unroll
        for (int kk = 0; kk < BK; kk++) {
            float a[4], wv[4];
            #pragma unroll
            for (int i = 0; i < 4; i++) a[i] = As[kk][tr * 4 + i];
            #pragma unroll
            for (int j = 0; j < 4; j++) wv[j] = Ws[kk][tc * 4 + j];
            #pragma unroll
            for (int i = 0; i < 4; i++)
                #pragma unroll
                for (int j = 0; j < 4; j++) acc[i][j] += a[i] * wv[j];
        }
        __syncthreads();
    }
    #pragma unroll
    for (int i = 0; i < 4; i++) {
        int gr = bm + tr * 4 + i;
        if (gr >= n) continue;
        #pragma unroll
        for (int j = 0; j < 4; j++) {
            int gc = bn + tc * 4 + j;
            if (gc < m) C[(size_t)gr * m + gc] = acc[i][j];
        }
    }
}

// ---------------------------------------------------------------------------
// out[i,j] = sw[i]*dinv[i]^2*hw[i,j] + b[j]
__global__ void init_out_kernel(const float* __restrict__ hw,
                                const float* __restrict__ sw,
                                const float* __restrict__ dinv,
                                const float* __restrict__ b,
                                float* __restrict__ out, int n, int m) {
    int idx = blockIdx.x * blockDim.x + threadIdx.x;
    if (idx >= n * m) return;
    int i = idx / m, j = idx - i * m;
    float dv = dinv[i];
    out[idx] = sw[i] * dv * dv * hw[idx] + b[j];
}

// warp per edge: out[dst] += ew*dinv[src]*dinv[dst]*hw[src]
__global__ void agg_kernel(const int* __restrict__ ei,
                           const float* __restrict__ w,
                           const float* __restrict__ dinv,
                           const float* __restrict__ hw,
                           float* __restrict__ out, int E, int m) {
    int e = (int)(((size_t)blockIdx.x * blockDim.x + threadIdx.x) >> 5);
    int lane = threadIdx.x & 31;
    if (e >= E) return;
    float ew = w[e];
    if (ew == 0.f) return;
    int s = ei[e];
    int t = ei[(size_t)E + e];
    float coef = ew * dinv[s] * dinv[t];
    const float* src_row = hw + (size_t)s * m;
    float* dst_row = out + (size_t)t * m;
    for (int j = lane; j < m; j += 32)
        atomicAdd(&dst_row[j], coef * src_row[j]);
}

__global__ void relu_kernel(float* __restrict__ x, int total) {
    int i = blockIdx.x * blockDim.x + threadIdx.x;
    if (i < total) x[i] = fmaxf(x[i], 0.f);
}

// warp per row log_softmax
__global__ void lsm_kernel(float* __restrict__ out, int n, int m) {
    int row = (blockIdx.x * blockDim.x + threadIdx.x) >> 5;
    int lane = threadIdx.x & 31;
    if (row >= n) return;
    float* r = out + (size_t)row * m;
    float mx = -1e30f;
    for (int j = lane; j < m; j += 32) mx = fmaxf(mx, r[j]);
    #pragma unroll
    for (int o = 16; o; o >>= 1) mx = fmaxf(mx, __shfl_xor_sync(0xffffffffu, mx, o));
    float se = 0.f;
    for (int j = lane; j < m; j += 32) se += expf(r[j] - mx);
    #pragma unroll
    for (int o = 16; o; o >>= 1) se += __shfl_xor_sync(0xffffffffu, se, o);
    float l = mx + logf(se);
    for (int j = lane; j < m; j += 32) r[j] -= l;
}

// ---------------------------------------------------------------------------
static void run_layer(const float* h, int d, const float* W, const float* b,
                      int dout, const int* ei, int n, int E,
                      float* hw, float* rowsum, float* deg, float* degG,
                      float* inv, float* w, float* sw, float* dinv,
                      float* out, bool do_relu) {
    const int T = 256;
    clear_kernel<<<(n + T - 1) / T, T>>>(rowsum, deg, degG, n);
    norm_kernel<<<(n * 32 + T - 1) / T, T>>>(h, inv, n, d);
    sim_kernel<<<(int)(((size_t)E * 32 + T - 1) / T), T>>>(h, ei, inv, w, rowsum, E, d);
    edge2_kernel<<<(E + T - 1) / T, T>>>(ei, w, rowsum, deg, degG, E);
    node2_kernel<<<(n + T - 1) / T, T>>>(deg, degG, sw, dinv, n);
    dim3 gg((dout + BN - 1) / BN, (n + BM - 1) / BM);
    gemm_kernel<<<gg, 256>>>(h, W, hw, n, d, dout);
    init_out_kernel<<<(n * dout + T - 1) / T, T>>>(hw, sw, dinv, b, out, n, dout);
    agg_kernel<<<(int)(((size_t)E * 32 + T - 1) / T), T>>>(ei, w, dinv, hw, out, E, dout);
    if (do_relu) relu_kernel<<<(n * dout + T - 1) / T, T>>>(out, n * dout);
}

extern "C" void kernel_launch(void* const* d_in, const int* in_sizes, int n_in,
                              void* d_out, int out_size) {
    const float* x = (const float*)d_in[0];
    const int* ei = (const int*)d_in[1];     // int32 (JAX default, no x64)
    const float* W1 = (const float*)d_in[2];
    const float* b1 = (const float*)d_in[3];
    const float* W2 = (const float*)d_in[4];
    const float* b2 = (const float*)d_in[5];
    const float* W3 = (const float*)d_in[6];
    const float* b3 = (const float*)d_in[7];
    float* out = (float*)d_out;

    int H  = in_sizes[3];          // 256
    int D2 = in_sizes[5];          // 64
    int C  = in_sizes[7];          // 40
    int F  = in_sizes[2] / H;      // 512
    int n  = in_sizes[0] / F;      // 50000
    int E  = in_sizes[1] / 2;      // 1600000

    float *p_h1, *p_h2, *p_hw, *p_w, *p_inv, *p_rowsum, *p_deg, *p_degG, *p_sw, *p_dinv;
    cudaGetSymbolAddress((void**)&p_h1, g_h1);
    cudaGetSymbolAddress((void**)&p_h2, g_h2);
    cudaGetSymbolAddress((void**)&p_hw, g_hw);
    cudaGetSymbolAddress((void**)&p_w, g_w);
    cudaGetSymbolAddress((void**)&p_inv, g_inv);
    cudaGetSymbolAddress((void**)&p_rowsum, g_rowsum);
    cudaGetSymbolAddress((void**)&p_deg, g_deg);
    cudaGetSymbolAddress((void**)&p_degG, g_degG);
    cudaGetSymbolAddress((void**)&p_sw, g_sw);
    cudaGetSymbolAddress((void**)&p_dinv, g_dinv);

    // Layer 1: x(512) -> h1(256), relu
    run_layer(x, F, W1, b1, H, ei, n, E, p_hw, p_rowsum, p_deg, p_degG,
              p_inv, p_w, p_sw, p_dinv, p_h1, true);
    // Layer 2: h1(256) -> h2(64), relu
    run_layer(p_h1, H, W2, b2, D2, ei, n, E, p_hw, p_rowsum, p_deg, p_degG,
              p_inv, p_w, p_sw, p_dinv, p_h2, true);
    // Layer 3: h2(64) -> out(40), no relu
    run_layer(p_h2, D2, W3, b3, C, ei, n, E, p_hw, p_rowsum, p_deg, p_degG,
              p_inv, p_w, p_sw, p_dinv, out, false);
    // log_softmax in place on d_out
    lsm_kernel<<<(n * 32 + 255) / 256, 256>>>(out, n, C);
}

// round 3
// speedup vs baseline: 1.3092x; 1.3092x over previous
#include <cuda_runtime.h>
#include <cstdint>

#define N_MAX 50000
#define E_MAX 1600000

// Scratch (device globals; allocations are forbidden)
__device__ __align__(16) float g_h1[N_MAX * 256];
__device__ __align__(16) float g_h2[N_MAX * 64];
__device__ __align__(16) float g_hw[N_MAX * 256];
__device__ float g_w[E_MAX];
__device__ float g_inv[N_MAX];
__device__ float g_rowsum[N_MAX];
__device__ float g_deg[N_MAX];
__device__ float g_degG[N_MAX];
__device__ float g_sw[N_MAX];
__device__ float g_dinv[N_MAX];
__device__ int g_rowptr[N_MAX + 1];
__device__ int g_ofs[N_MAX];
__device__ int g_eid[E_MAX];

// ---------------------------------------------------------------------------
__global__ void clear3_kernel(float* a, float* b, float* c, int n) {
    int i = blockIdx.x * blockDim.x + threadIdx.x;
    if (i < n) { a[i] = 0.f; b[i] = 0.f; c[i] = 0.f; }
}

__global__ void zeroi_kernel(int* a, int n) {
    int i = blockIdx.x * blockDim.x + threadIdx.x;
    if (i < n) a[i] = 0;
}

// ---------------------------------------------------------------------------
// CSR-by-dst build
__global__ void hist_kernel(const int* __restrict__ ei, int* __restrict__ rowptr, int E) {
    int e = blockIdx.x * blockDim.x + threadIdx.x;
    if (e < E) atomicAdd(&rowptr[ei[(size_t)E + e] + 1], 1);
}

// single-block inclusive scan over n ints (warp-shuffle based)
__global__ void scan_kernel(int* __restrict__ data, int n) {
    __shared__ int wsum[32];
    __shared__ int carry_s;
    int lane = threadIdx.x & 31, wid = threadIdx.x >> 5;
    if (threadIdx.x == 0) carry_s = 0;
    __syncthreads();
    for (int base = 0; base < n; base += 1024) {
        int i = base + threadIdx.x;
        int v = (i < n) ? data[i] : 0;
        int x = v;
        #pragma unroll
        for (int o = 1; o < 32; o <<= 1) {
            int t = __shfl_up_sync(0xffffffffu, x, o);
            if (lane >= o) x += t;
        }
        if (lane == 31) wsum[wid] = x;
        __syncthreads();
        if (wid == 0) {
            int ws = wsum[lane];
            #pragma unroll
            for (int o = 1; o < 32; o <<= 1) {
                int t = __shfl_up_sync(0xffffffffu, ws, o);
                if (lane >= o) ws += t;
            }
            wsum[lane] = ws;
        }
        __syncthreads();
        int offset = (wid > 0) ? wsum[wid - 1] : 0;
        int carry = carry_s;
        if (i < n) data[i] = x + offset + carry;
        __syncthreads();
        if (threadIdx.x == 1023) carry_s = carry + wsum[31];
        __syncthreads();
    }
}

__global__ void copyofs_kernel(const int* __restrict__ rowptr, int* __restrict__ ofs, int n) {
    int i = blockIdx.x * blockDim.x + threadIdx.x;
    if (i < n) ofs[i] = rowptr[i];
}

__global__ void scatter_kernel(const int* __restrict__ ei, int* __restrict__ ofs,
                               int* __restrict__ eid, int E) {
    int e = blockIdx.x * blockDim.x + threadIdx.x;
    if (e < E) {
        int pos = atomicAdd(&ofs[ei[(size_t)E + e]], 1);
        eid[pos] = e;
    }
}

// ---------------------------------------------------------------------------
// per-node inverse L2 norm (zero rows -> 1), float4
__global__ void norm_kernel(const float* __restrict__ h, float* __restrict__ inv,
                            int n, int d4) {
    int warp = (blockIdx.x * blockDim.x + threadIdx.x) >> 5;
    int lane = threadIdx.x & 31;
    if (warp >= n) return;
    const float4* row = (const float4*)h + (size_t)warp * d4;
    float acc = 0.f;
    for (int k = lane; k < d4; k += 32) {
        float4 v = row[k];
        acc += v.x * v.x + v.y * v.y + v.z * v.z + v.w * v.w;
    }
    #pragma unroll
    for (int o = 16; o; o >>= 1) acc += __shfl_xor_sync(0xffffffffu, acc, o);
    if (lane == 0) inv[warp] = (acc == 0.f) ? 1.f : rsqrtf(acc) ;
}

// per-edge cosine sim + threshold + rowsum accumulation, float4
__global__ void sim_kernel(const float* __restrict__ h,
                           const int* __restrict__ ei,
                           const float* __restrict__ inv,
                           float* __restrict__ w, float* __restrict__ rowsum,
                           int E, int d4) {
    int warp = (int)(((size_t)blockIdx.x * blockDim.x + threadIdx.x) >> 5);
    int lane = threadIdx.x & 31;
    if (warp >= E) return;
    int s = ei[warp];
    int t = ei[(size_t)E + warp];
    const float4* hs = (const float4*)h + (size_t)s * d4;
    const float4* ht = (const float4*)h + (size_t)t * d4;
    float acc = 0.f;
    for (int k = lane; k < d4; k += 32) {
        float4 a = hs[k], b = ht[k];
        acc += a.x * b.x + a.y * b.y + a.z * b.z + a.w * b.w;
    }
    #pragma unroll
    for (int o = 16; o; o >>= 1) acc += __shfl_xor_sync(0xffffffffu, acc, o);
    if (lane == 0) {
        float sim = acc * inv[s] * inv[t];
        float wv = (s != t && sim >= 0.f) ? sim : 0.f;
        w[warp] = wv;
        if (wv > 0.f) atomicAdd(&rowsum[s], wv);
    }
}

// per-edge: L1 normalize, exp, deg count, GCN degree accumulation
__global__ void edge2_kernel(const int* __restrict__ ei,
                             float* __restrict__ w,
                             const float* __restrict__ rowsum,
                             float* __restrict__ deg, float* __restrict__ degG,
                             int E) {
    int e = blockIdx.x * blockDim.x + threadIdx.x;
    if (e >= E) return;
    float wv = w[e];
    float ew = 0.f;
    if (wv > 0.f) {
        int s = ei[e];
        ew = expf(wv / rowsum[s]);
        atomicAdd(&deg[s], 1.0f);
        atomicAdd(&degG[ei[(size_t)E + e]], ew);
    }
    w[e] = ew;
}

__global__ void node2_kernel(const float* __restrict__ deg,
                             const float* __restrict__ degG,
                             float* __restrict__ sw, float* __restrict__ dinv,
                             int n) {
    int i = blockIdx.x * blockDim.x + threadIdx.x;
    if (i >= n) return;
    float s = expf(1.0f / (deg[i] + 1.0f));
    sw[i] = s;
    dinv[i] = rsqrtf(degG[i] + s);
}

// ---------------------------------------------------------------------------
// GEMM: C[n x m] = A[n x k] * W[k x m]; 128x64 tile, 8x4 micro, 256 threads
#define GM 128
#define GN 64
#define GK 16
__global__ void gemm_kernel(const float* __restrict__ A,
                            const float* __restrict__ W,
                            float* __restrict__ C, int n, int k, int m) {
    __shared__ float As[GK][GM];
    __shared__ float Ws[GK][GN];
    int bm = blockIdx.y * GM;
    int bn = blockIdx.x * GN;
    int tid = threadIdx.x;
    int tr = tid >> 4, tc = tid & 15;     // 16 x 16 thread grid
    float acc[8][4] = {};
    for (int k0 = 0; k0 < k; k0 += GK) {
        // A tile: 128x16 = 512 float4; 2 per thread
        #pragma unroll
        for (int l = 0; l < 2; l++) {
            int f = tid * 2 + l;          // 0..511
            int r = f >> 2;               // 0..127
            int c4 = (f & 3) * 4;         // 0,4,8,12
            int gr = bm + r;
            float4 v = make_float4(0.f, 0.f, 0.f, 0.f);
            if (gr < n) v = *(const float4*)&A[(size_t)gr * k + k0 + c4];
            As[c4 + 0][r] = v.x; As[c4 + 1][r] = v.y;
            As[c4 + 2][r] = v.z; As[c4 + 3][r] = v.w;
        }
        // W tile: 16x64 = 256 float4; 1 per thread
        {
            int r = tid >> 4;             // 0..15
            int c4 = (tid & 15) * 4;      // 0..60
            int gc = bn + c4;
            const float* wrow = &W[(size_t)(k0 + r) * m];
            float4 v;
            if (gc + 3 < m) v = *(const float4*)&wrow[gc];
            else {
                v.x = (gc + 0 < m) ? wrow[gc + 0] : 0.f;
                v.y = (gc + 1 < m) ? wrow[gc + 1] : 0.f;
                v.z = (gc + 2 < m) ? wrow[gc + 2] : 0.f;
                v.w = (gc + 3 < m) ? wrow[gc + 3] : 0.f;
            }
            *(float4*)&Ws[r][c4] = v;
        }
        __syncthreads();
        #pragma unroll
        for (int kk = 0; kk < GK; kk++) {
            float a[8];
            *(float4*)&a[0] = *(float4*)&As[kk][tr * 8];
            *(float4*)&a[4] = *(float4*)&As[kk][tr * 8 + 4];
            float4 wv = *(float4*)&Ws[kk][tc * 4];
            #pragma unroll
            for (int i = 0; i < 8; i++) {
                acc[i][0] += a[i] * wv.x;
                acc[i][1] += a[i] * wv.y;
                acc[i][2] += a[i] * wv.z;
                acc[i][3] += a[i] * wv.w;
            }
        }
        __syncthreads();
    }
    #pragma unroll
    for (int i = 0; i < 8; i++) {
        int gr = bm + tr * 8 + i;
        if (gr >= n) continue;
        int gc = bn + tc * 4;
        if (gc + 3 < m) {
            float4 v = make_float4(acc[i][0], acc[i][1], acc[i][2], acc[i][3]);
            *(float4*)&C[(size_t)gr * m + gc] = v;
        } else {
            #pragma unroll
            for (int j = 0; j < 4; j++)
                if (gc + j < m) C[(size_t)gr * m + gc + j] = acc[i][j];
        }
    }
}

// ---------------------------------------------------------------------------
// CSR aggregation, fused with self-loop term + bias + optional relu.
// warp per dst node; VPT float4 accumulators per lane.
template <int VPT>
__global__ void agg_csr_kernel(const int* __restrict__ ei,
                               const int* __restrict__ rowptr,
                               const int* __restrict__ eid,
                               const float* __restrict__ w,
                               const float* __restrict__ dinv,
                               const float* __restrict__ sw,
                               const float* __restrict__ hw,
                               const float* __restrict__ b,
                               float* __restrict__ out,
                               int n, int E, int m4, int relu) {
    int node = (int)(((size_t)blockIdx.x * blockDim.x + threadIdx.x) >> 5);
    int lane = threadIdx.x & 31;
    if (node >= n) return;
    float4 acc[VPT];
    #pragma unroll
    for (int v = 0; v < VPT; v++) acc[v] = make_float4(0.f, 0.f, 0.f, 0.f);
    float dt = dinv[node];
    int p0 = rowptr[node], p1 = rowptr[node + 1];
    const float4* hw4 = (const float4*)hw;
    for (int p = p0; p < p1; p++) {
        int e = eid[p];
        float ew = w[e];
        if (ew == 0.f) continue;
        int s = ei[e];
        float coef = ew * dinv[s] * dt;
        const float4* row = hw4 + (size_t)s * m4;
        #pragma unroll
        for (int v = 0; v < VPT; v++) {
            int j = lane + v * 32;
            if (j < m4) {
                float4 hv = row[j];
                acc[v].x += coef * hv.x; acc[v].y += coef * hv.y;
                acc[v].z += coef * hv.z; acc[v].w += coef * hv.w;
            }
        }
    }
    float self = sw[node] * dt * dt;
    const float4* srow = hw4 + (size_t)node * m4;
    float4* orow = (float4*)out + (size_t)node * m4;
    const float4* b4 = (const float4*)b;
    #pragma unroll
    for (int v = 0; v < VPT; v++) {
        int j = lane + v * 32;
        if (j < m4) {
            float4 hv = srow[j];
            float4 bv = b4[j];
            float4 r;
            r.x = acc[v].x + self * hv.x + bv.x;
            r.y = acc[v].y + self * hv.y + bv.y;
            r.z = acc[v].z + self * hv.z + bv.z;
            r.w = acc[v].w + self * hv.w + bv.w;
            if (relu) {
                r.x = fmaxf(r.x, 0.f); r.y = fmaxf(r.y, 0.f);
                r.z = fmaxf(r.z, 0.f); r.w = fmaxf(r.w, 0.f);
            }
            orow[j] = r;
        }
    }
}

// warp per row log_softmax
__global__ void lsm_kernel(float* __restrict__ out, int n, int m) {
    int row = (blockIdx.x * blockDim.x + threadIdx.x) >> 5;
    int lane = threadIdx.x & 31;
    if (row >= n) return;
    float* r = out + (size_t)row * m;
    float mx = -1e30f;
    for (int j = lane; j < m; j += 32) mx = fmaxf(mx, r[j]);
    #pragma unroll
    for (int o = 16; o; o >>= 1) mx = fmaxf(mx, __shfl_xor_sync(0xffffffffu, mx, o));
    float se = 0.f;
    for (int j = lane; j < m; j += 32) se += expf(r[j] - mx);
    #pragma unroll
    for (int o = 16; o; o >>= 1) se += __shfl_xor_sync(0xffffffffu, se, o);
    float l = mx + logf(se);
    for (int j = lane; j < m; j += 32) r[j] -= l;
}

// ---------------------------------------------------------------------------
static void run_layer(const float* h, int d, const float* W, const float* b,
                      int dout, const int* ei, int n, int E,
                      float* hw, float* rowsum, float* deg, float* degG,
                      float* inv, float* w, float* sw, float* dinv,
                      const int* rowptr, const int* eid,
                      float* out, bool do_relu) {
    const int T = 256;
    clear3_kernel<<<(n + T - 1) / T, T>>>(rowsum, deg, degG, n);
    norm_kernel<<<(n * 32 + T - 1) / T, T>>>(h, inv, n, d >> 2);
    sim_kernel<<<(int)(((size_t)E * 32 + T - 1) / T), T>>>(h, ei, inv, w, rowsum, E, d >> 2);
    edge2_kernel<<<(E + T - 1) / T, T>>>(ei, w, rowsum, deg, degG, E);
    node2_kernel<<<(n + T - 1) / T, T>>>(deg, degG, sw, dinv, n);
    dim3 gg((dout + GN - 1) / GN, (n + GM - 1) / GM);
    gemm_kernel<<<gg, 256>>>(h, W, hw, n, d, dout);
    int m4 = dout >> 2;
    int blocks = (int)(((size_t)n * 32 + T - 1) / T);
    if (m4 > 32)
        agg_csr_kernel<2><<<blocks, T>>>(ei, rowptr, eid, w, dinv, sw, hw, b, out,
                                         n, E, m4, do_relu ? 1 : 0);
    else
        agg_csr_kernel<1><<<blocks, T>>>(ei, rowptr, eid, w, dinv, sw, hw, b, out,
                                         n, E, m4, do_relu ? 1 : 0);
}

extern "C" void kernel_launch(void* const* d_in, const int* in_sizes, int n_in,
                              void* d_out, int out_size) {
    const float* x = (const float*)d_in[0];
    const int* ei = (const int*)d_in[1];     // int32 (JAX default)
    const float* W1 = (const float*)d_in[2];
    const float* b1 = (const float*)d_in[3];
    const float* W2 = (const float*)d_in[4];
    const float* b2 = (const float*)d_in[5];
    const float* W3 = (const float*)d_in[6];
    const float* b3 = (const float*)d_in[7];
    float* out = (float*)d_out;

    int H  = in_sizes[3];          // 256
    int D2 = in_sizes[5];          // 64
    int C  = in_sizes[7];          // 40
    int F  = in_sizes[2] / H;      // 512
    int n  = in_sizes[0] / F;      // 50000
    int E  = in_sizes[1] / 2;      // 1600000

    float *p_h1, *p_h2, *p_hw, *p_w, *p_inv, *p_rowsum, *p_deg, *p_degG, *p_sw, *p_dinv;
    int *p_rowptr, *p_ofs, *p_eid;
    cudaGetSymbolAddress((void**)&p_h1, g_h1);
    cudaGetSymbolAddress((void**)&p_h2, g_h2);
    cudaGetSymbolAddress((void**)&p_hw, g_hw);
    cudaGetSymbolAddress((void**)&p_w, g_w);
    cudaGetSymbolAddress((void**)&p_inv, g_inv);
    cudaGetSymbolAddress((void**)&p_rowsum, g_rowsum);
    cudaGetSymbolAddress((void**)&p_deg, g_deg);
    cudaGetSymbolAddress((void**)&p_degG, g_degG);
    cudaGetSymbolAddress((void**)&p_sw, g_sw);
    cudaGetSymbolAddress((void**)&p_dinv, g_dinv);
    cudaGetSymbolAddress((void**)&p_rowptr, g_rowptr);
    cudaGetSymbolAddress((void**)&p_ofs, g_ofs);
    cudaGetSymbolAddress((void**)&p_eid, g_eid);

    const int T = 256;
    // Build CSR by dst once (edge structure identical across layers)
    zeroi_kernel<<<(n + 1 + T - 1) / T, T>>>(p_rowptr, n + 1);
    hist_kernel<<<(E + T - 1) / T, T>>>(ei, p_rowptr, E);
    scan_kernel<<<1, 1024>>>(p_rowptr, n + 1);
    copyofs_kernel<<<(n + T - 1) / T, T>>>(p_rowptr, p_ofs, n);
    scatter_kernel<<<(E + T - 1) / T, T>>>(ei, p_ofs, p_eid, E);

    // Layer 1: x(512) -> h1(256), relu
    run_layer(x, F, W1, b1, H, ei, n, E, p_hw, p_rowsum, p_deg, p_degG,
              p_inv, p_w, p_sw, p_dinv, p_rowptr, p_eid, p_h1, true);
    // Layer 2: h1(256) -> h2(64), relu
    run_layer(p_h1, H, W2, b2, D2, ei, n, E, p_hw, p_rowsum, p_deg, p_degG,
              p_inv, p_w, p_sw, p_dinv, p_rowptr, p_eid, p_h2, true);
    // Layer 3: h2(64) -> out(40), no relu
    run_layer(p_h2, D2, W3, b3, C, ei, n, E, p_hw, p_rowsum, p_deg, p_degG,
              p_inv, p_w, p_sw, p_dinv, p_rowptr, p_eid, out, false);
    // log_softmax in place on d_out
    lsm_kernel<<<(n * 32 + 255) / 256, 256>>>(out, n, C);
}

// round 4
// speedup vs baseline: 1.7126x; 1.3082x over previous
#include <cuda_runtime.h>
#include <cstdint>

#define N_MAX 50000
#define E_MAX 1600000

// Scratch (device globals; allocations are forbidden)
__device__ __align__(16) float g_h1[N_MAX * 256];
__device__ __align__(16) float g_h2[N_MAX * 64];
__device__ __align__(16) float g_hw[N_MAX * 256];
__device__ float g_w[E_MAX];        // CSR-ordered edge weights
__device__ float g_inv[N_MAX];
__device__ float g_rowsum[N_MAX];
__device__ float g_deg[N_MAX];
__device__ float g_degG[N_MAX];
__device__ float g_sw[N_MAX];
__device__ float g_dinv[N_MAX];
__device__ int g_rowptr[N_MAX + 1];
__device__ int g_ofs[N_MAX];
__device__ int g_esrc[E_MAX];       // src node per CSR slot (dst-grouped)

// ---------------------------------------------------------------------------
__global__ void clear2_kernel(float* a, float* b, int n) {
    int i = blockIdx.x * blockDim.x + threadIdx.x;
    if (i < n) { a[i] = 0.f; b[i] = 0.f; }
}

__global__ void zeroi_kernel(int* a, int n) {
    int i = blockIdx.x * blockDim.x + threadIdx.x;
    if (i < n) a[i] = 0;
}

// ---------------------------------------------------------------------------
// CSR-by-dst build
__global__ void hist_kernel(const int* __restrict__ ei, int* __restrict__ rowptr, int E) {
    int e = blockIdx.x * blockDim.x + threadIdx.x;
    if (e < E) atomicAdd(&rowptr[ei[(size_t)E + e] + 1], 1);
}

// single-block inclusive scan over n ints (warp-shuffle based)
__global__ void scan_kernel(int* __restrict__ data, int n) {
    __shared__ int wsum[32];
    __shared__ int carry_s;
    int lane = threadIdx.x & 31, wid = threadIdx.x >> 5;
    if (threadIdx.x == 0) carry_s = 0;
    __syncthreads();
    for (int base = 0; base < n; base += 1024) {
        int i = base + threadIdx.x;
        int v = (i < n) ? data[i] : 0;
        int x = v;
        #pragma unroll
        for (int o = 1; o < 32; o <<= 1) {
            int t = __shfl_up_sync(0xffffffffu, x, o);
            if (lane >= o) x += t;
        }
        if (lane == 31) wsum[wid] = x;
        __syncthreads();
        if (wid == 0) {
            int ws = wsum[lane];
            #pragma unroll
            for (int o = 1; o < 32; o <<= 1) {
                int t = __shfl_up_sync(0xffffffffu, ws, o);
                if (lane >= o) ws += t;
            }
            wsum[lane] = ws;
        }
        __syncthreads();
        int offset = (wid > 0) ? wsum[wid - 1] : 0;
        int carry = carry_s;
        if (i < n) data[i] = x + offset + carry;
        __syncthreads();
        if (threadIdx.x == 1023) carry_s = carry + wsum[31];
        __syncthreads();
    }
}

__global__ void copyofs_kernel(const int* __restrict__ rowptr, int* __restrict__ ofs, int n) {
    int i = blockIdx.x * blockDim.x + threadIdx.x;
    if (i < n) ofs[i] = rowptr[i];
}

// store SRC id directly into the dst-CSR slot
__global__ void scatter_kernel(const int* __restrict__ ei, int* __restrict__ ofs,
                               int* __restrict__ esrc, int E) {
    int e = blockIdx.x * blockDim.x + threadIdx.x;
    if (e < E) {
        int pos = atomicAdd(&ofs[ei[(size_t)E + e]], 1);
        esrc[pos] = ei[e];
    }
}

// ---------------------------------------------------------------------------
// per-node inverse L2 norm (zero rows -> 1), float4
__global__ void norm_kernel(const float* __restrict__ h, float* __restrict__ inv,
                            int n, int d4) {
    int warp = (blockIdx.x * blockDim.x + threadIdx.x) >> 5;
    int lane = threadIdx.x & 31;
    if (warp >= n) return;
    const float4* row = (const float4*)h + (size_t)warp * d4;
    float acc = 0.f;
    for (int k = lane; k < d4; k += 32) {
        float4 v = row[k];
        acc += v.x * v.x + v.y * v.y + v.z * v.z + v.w * v.w;
    }
    #pragma unroll
    for (int o = 16; o; o >>= 1) acc += __shfl_xor_sync(0xffffffffu, acc, o);
    if (lane == 0) inv[warp] = (acc == 0.f) ? 1.f : rsqrtf(acc);
}

// warp per dst node: dst row cached in registers; per edge dot vs src row.
// Writes w in CSR order; accumulates rowsum[src] via atomics.
template <int VPT>
__global__ void sim_csr_kernel(const float* __restrict__ h,
                               const int* __restrict__ rowptr,
                               const int* __restrict__ esrc,
                               const float* __restrict__ inv,
                               float* __restrict__ w, float* __restrict__ rowsum,
                               int n, int d4) {
    int node = (int)(((size_t)blockIdx.x * blockDim.x + threadIdx.x) >> 5);
    int lane = threadIdx.x & 31;
    if (node >= n) return;
    const float4* h4 = (const float4*)h;
    const float4* ht = h4 + (size_t)node * d4;
    float4 cached[VPT];
    #pragma unroll
    for (int v = 0; v < VPT; v++) {
        int j = lane + v * 32;
        cached[v] = (j < d4) ? ht[j] : make_float4(0.f, 0.f, 0.f, 0.f);
    }
    float invt = inv[node];
    int p0 = rowptr[node], p1 = rowptr[node + 1];
    for (int p = p0; p < p1; p++) {
        int s = esrc[p];
        const float4* hs = h4 + (size_t)s * d4;
        float acc = 0.f;
        #pragma unroll
        for (int v = 0; v < VPT; v++) {
            int j = lane + v * 32;
            if (j < d4) {
                float4 a = hs[j], b = cached[v];
                acc += a.x * b.x + a.y * b.y + a.z * b.z + a.w * b.w;
            }
        }
        #pragma unroll
        for (int o = 16; o; o >>= 1) acc += __shfl_xor_sync(0xffffffffu, acc, o);
        if (lane == 0) {
            float sim = acc * inv[s] * invt;
            float wv = (s != node && sim >= 0.f) ? sim : 0.f;
            w[p] = wv;
            if (wv > 0.f) atomicAdd(&rowsum[s], wv);
        }
    }
}

// thread per dst node: normalize+exp each incoming edge; deg[src] atomics;
// degG[dst] is a plain register sum (no atomic, no clear).
__global__ void edge2_csr_kernel(const int* __restrict__ rowptr,
                                 const int* __restrict__ esrc,
                                 float* __restrict__ w,
                                 const float* __restrict__ rowsum,
                                 float* __restrict__ deg, float* __restrict__ degG,
                                 int n) {
    int t = blockIdx.x * blockDim.x + threadIdx.x;
    if (t >= n) return;
    int p0 = rowptr[t], p1 = rowptr[t + 1];
    float dsum = 0.f;
    for (int p = p0; p < p1; p++) {
        float wv = w[p];
        if (wv > 0.f) {
            int s = esrc[p];
            float ew = expf(wv / rowsum[s]);
            atomicAdd(&deg[s], 1.0f);
            dsum += ew;
            w[p] = ew;
        }
    }
    degG[t] = dsum;
}

__global__ void node2_kernel(const float* __restrict__ deg,
                             const float* __restrict__ degG,
                             float* __restrict__ sw, float* __restrict__ dinv,
                             int n) {
    int i = blockIdx.x * blockDim.x + threadIdx.x;
    if (i >= n) return;
    float s = expf(1.0f / (deg[i] + 1.0f));
    sw[i] = s;
    dinv[i] = rsqrtf(degG[i] + s);
}

// ---------------------------------------------------------------------------
// GEMM A: 128x128 tile, 8x8 micro, 256 threads (m % 128 == 0, k % 16 == 0)
__global__ void __launch_bounds__(256) gemm128_kernel(
        const float* __restrict__ A, const float* __restrict__ W,
        float* __restrict__ C, int n, int k, int m) {
    __shared__ float As[16][128];
    __shared__ float Ws[16][128];
    int bm = blockIdx.y * 128;
    int bn = blockIdx.x * 128;
    int tid = threadIdx.x;
    int tr = tid >> 4, tc = tid & 15;
    float acc[8][8] = {};
    for (int k0 = 0; k0 < k; k0 += 16) {
        #pragma unroll
        for (int l = 0; l < 2; l++) {
            int f = tid * 2 + l;          // 0..511
            int r = f >> 2;               // 0..127
            int c4 = (f & 3) * 4;
            int gr = bm + r;
            float4 v = make_float4(0.f, 0.f, 0.f, 0.f);
            if (gr < n) v = *(const float4*)&A[(size_t)gr * k + k0 + c4];
            As[c4 + 0][r] = v.x; As[c4 + 1][r] = v.y;
            As[c4 + 2][r] = v.z; As[c4 + 3][r] = v.w;
        }
        #pragma unroll
        for (int l = 0; l < 2; l++) {
            int f = tid * 2 + l;          // 0..511
            int r = f >> 5;               // 0..15
            int c4 = (f & 31) * 4;        // 0..124
            float4 v = *(const float4*)&W[(size_t)(k0 + r) * m + bn + c4];
            *(float4*)&Ws[r][c4] = v;
        }
        __syncthreads();
        #pragma unroll
        for (int kk = 0; kk < 16; kk++) {
            float a[8], wv[8];
            *(float4*)&a[0] = *(float4*)&As[kk][tr * 8];
            *(float4*)&a[4] = *(float4*)&As[kk][tr * 8 + 4];
            *(float4*)&wv[0] = *(float4*)&Ws[kk][tc * 8];
            *(float4*)&wv[4] = *(float4*)&Ws[kk][tc * 8 + 4];
            #pragma unroll
            for (int i = 0; i < 8; i++)
                #pragma unroll
                for (int j = 0; j < 8; j++) acc[i][j] += a[i] * wv[j];
        }
        __syncthreads();
    }
    #pragma unroll
    for (int i = 0; i < 8; i++) {
        int gr = bm + tr * 8 + i;
        if (gr >= n) continue;
        float* crow = &C[(size_t)gr * m + bn + tc * 8];
        *(float4*)&crow[0] = make_float4(acc[i][0], acc[i][1], acc[i][2], acc[i][3]);
        *(float4*)&crow[4] = make_float4(acc[i][4], acc[i][5], acc[i][6], acc[i][7]);
    }
}

// GEMM B: 128x64 tile, 8x4 micro, 256 threads (general m, k % 16 == 0)
__global__ void __launch_bounds__(256) gemm64_kernel(
        const float* __restrict__ A, const float* __restrict__ W,
        float* __restrict__ C, int n, int k, int m) {
    __shared__ float As[16][128];
    __shared__ float Ws[16][64];
    int bm = blockIdx.y * 128;
    int bn = blockIdx.x * 64;
    int tid = threadIdx.x;
    int tr = tid >> 4, tc = tid & 15;
    float acc[8][4] = {};
    for (int k0 = 0; k0 < k; k0 += 16) {
        #pragma unroll
        for (int l = 0; l < 2; l++) {
            int f = tid * 2 + l;
            int r = f >> 2;
            int c4 = (f & 3) * 4;
            int gr = bm + r;
            float4 v = make_float4(0.f, 0.f, 0.f, 0.f);
            if (gr < n) v = *(const float4*)&A[(size_t)gr * k + k0 + c4];
            As[c4 + 0][r] = v.x; As[c4 + 1][r] = v.y;
            As[c4 + 2][r] = v.z; As[c4 + 3][r] = v.w;
        }
        {
            int r = tid >> 4;
            int c4 = (tid & 15) * 4;
            int gc = bn + c4;
            const float* wrow = &W[(size_t)(k0 + r) * m];
            float4 v;
            if (gc + 3 < m) v = *(const float4*)&wrow[gc];
            else {
                v.x = (gc + 0 < m) ? wrow[gc + 0] : 0.f;
                v.y = (gc + 1 < m) ? wrow[gc + 1] : 0.f;
                v.z = (gc + 2 < m) ? wrow[gc + 2] : 0.f;
                v.w = (gc + 3 < m) ? wrow[gc + 3] : 0.f;
            }
            *(float4*)&Ws[r][c4] = v;
        }
        __syncthreads();
        #pragma unroll
        for (int kk = 0; kk < 16; kk++) {
            float a[8];
            *(float4*)&a[0] = *(float4*)&As[kk][tr * 8];
            *(float4*)&a[4] = *(float4*)&As[kk][tr * 8 + 4];
            float4 wv = *(float4*)&Ws[kk][tc * 4];
            #pragma unroll
            for (int i = 0; i < 8; i++) {
                acc[i][0] += a[i] * wv.x;
                acc[i][1] += a[i] * wv.y;
                acc[i][2] += a[i] * wv.z;
                acc[i][3] += a[i] * wv.w;
            }
        }
        __syncthreads();
    }
    #pragma unroll
    for (int i = 0; i < 8; i++) {
        int gr = bm + tr * 8 + i;
        if (gr >= n) continue;
        int gc = bn + tc * 4;
        if (gc + 3 < m) {
            *(float4*)&C[(size_t)gr * m + gc] =
                make_float4(acc[i][0], acc[i][1], acc[i][2], acc[i][3]);
        } else {
            #pragma unroll
            for (int j = 0; j < 4; j++)
                if (gc + j < m) C[(size_t)gr * m + gc + j] = acc[i][j];
        }
    }
}

// ---------------------------------------------------------------------------
// CSR aggregation, fused self-loop + bias + optional relu. warp per dst node.
template <int VPT>
__global__ void agg_csr_kernel(const int* __restrict__ rowptr,
                               const int* __restrict__ esrc,
                               const float* __restrict__ w,
                               const float* __restrict__ dinv,
                               const float* __restrict__ sw,
                               const float* __restrict__ hw,
                               const float* __restrict__ b,
                               float* __restrict__ out,
                               int n, int m4, int relu) {
    int node = (int)(((size_t)blockIdx.x * blockDim.x + threadIdx.x) >> 5);
    int lane = threadIdx.x & 31;
    if (node >= n) return;
    float4 acc[VPT];
    #pragma unroll
    for (int v = 0; v < VPT; v++) acc[v] = make_float4(0.f, 0.f, 0.f, 0.f);
    float dt = dinv[node];
    int p0 = rowptr[node], p1 = rowptr[node + 1];
    const float4* hw4 = (const float4*)hw;
    for (int p = p0; p < p1; p++) {
        float ew = w[p];
        if (ew == 0.f) continue;
        int s = esrc[p];
        float coef = ew * dinv[s] * dt;
        const float4* row = hw4 + (size_t)s * m4;
        #pragma unroll
        for (int v = 0; v < VPT; v++) {
            int j = lane + v * 32;
            if (j < m4) {
                float4 hv = row[j];
                acc[v].x += coef * hv.x; acc[v].y += coef * hv.y;
                acc[v].z += coef * hv.z; acc[v].w += coef * hv.w;
            }
        }
    }
    float self = sw[node] * dt * dt;
    const float4* srow = hw4 + (size_t)node * m4;
    float4* orow = (float4*)out + (size_t)node * m4;
    const float4* b4 = (const float4*)b;
    #pragma unroll
    for (int v = 0; v < VPT; v++) {
        int j = lane + v * 32;
        if (j < m4) {
            float4 hv = srow[j];
            float4 bv = b4[j];
            float4 r;
            r.x = acc[v].x + self * hv.x + bv.x;
            r.y = acc[v].y + self * hv.y + bv.y;
            r.z = acc[v].z + self * hv.z + bv.z;
            r.w = acc[v].w + self * hv.w + bv.w;
            if (relu) {
                r.x = fmaxf(r.x, 0.f); r.y = fmaxf(r.y, 0.f);
                r.z = fmaxf(r.z, 0.f); r.w = fmaxf(r.w, 0.f);
            }
            orow[j] = r;
        }
    }
}

// warp per row log_softmax
__global__ void lsm_kernel(float* __restrict__ out, int n, int m) {
    int row = (blockIdx.x * blockDim.x + threadIdx.x) >> 5;
    int lane = threadIdx.x & 31;
    if (row >= n) return;
    float* r = out + (size_t)row * m;
    float mx = -1e30f;
    for (int j = lane; j < m; j += 32) mx = fmaxf(mx, r[j]);
    #pragma unroll
    for (int o = 16; o; o >>= 1) mx = fmaxf(mx, __shfl_xor_sync(0xffffffffu, mx, o));
    float se = 0.f;
    for (int j = lane; j < m; j += 32) se += expf(r[j] - mx);
    #pragma unroll
    for (int o = 16; o; o >>= 1) se += __shfl_xor_sync(0xffffffffu, se, o);
    float l = mx + logf(se);
    for (int j = lane; j < m; j += 32) r[j] -= l;
}

// ---------------------------------------------------------------------------
static void run_layer(const float* h, int d, const float* W, const float* b,
                      int dout, int n,
                      float* hw, float* rowsum, float* deg, float* degG,
                      float* inv, float* w, float* sw, float* dinv,
                      const int* rowptr, const int* esrc,
                      float* out, bool do_relu) {
    const int T = 256;
    int d4 = d >> 2;
    clear2_kernel<<<(n + T - 1) / T, T>>>(rowsum, deg, n);
    norm_kernel<<<(n * 32 + T - 1) / T, T>>>(h, inv, n, d4);
    int simblocks = (int)(((size_t)n * 32 + T - 1) / T);
    if (d4 > 64)
        sim_csr_kernel<4><<<simblocks, T>>>(h, rowptr, esrc, inv, w, rowsum, n, d4);
    else if (d4 > 32)
        sim_csr_kernel<2><<<simblocks, T>>>(h, rowptr, esrc, inv, w, rowsum, n, d4);
    else
        sim_csr_kernel<1><<<simblocks, T>>>(h, rowptr, esrc, inv, w, rowsum, n, d4);
    edge2_csr_kernel<<<(n + T - 1) / T, T>>>(rowptr, esrc, w, rowsum, deg, degG, n);
    node2_kernel<<<(n + T - 1) / T, T>>>(deg, degG, sw, dinv, n);
    if ((dout & 127) == 0) {
        dim3 gg(dout / 128, (n + 127) / 128);
        gemm128_kernel<<<gg, 256>>>(h, W, hw, n, d, dout);
    } else {
        dim3 gg((dout + 63) / 64, (n + 127) / 128);
        gemm64_kernel<<<gg, 256>>>(h, W, hw, n, d, dout);
    }
    int m4 = dout >> 2;
    if (m4 > 32)
        agg_csr_kernel<2><<<simblocks, T>>>(rowptr, esrc, w, dinv, sw, hw, b, out,
                                            n, m4, do_relu ? 1 : 0);
    else
        agg_csr_kernel<1><<<simblocks, T>>>(rowptr, esrc, w, dinv, sw, hw, b, out,
                                            n, m4, do_relu ? 1 : 0);
}

extern "C" void kernel_launch(void* const* d_in, const int* in_sizes, int n_in,
                              void* d_out, int out_size) {
    const float* x = (const float*)d_in[0];
    const int* ei = (const int*)d_in[1];     // int32 (JAX default)
    const float* W1 = (const float*)d_in[2];
    const float* b1 = (const float*)d_in[3];
    const float* W2 = (const float*)d_in[4];
    const float* b2 = (const float*)d_in[5];
    const float* W3 = (const float*)d_in[6];
    const float* b3 = (const float*)d_in[7];
    float* out = (float*)d_out;

    int H  = in_sizes[3];          // 256
    int D2 = in_sizes[5];          // 64
    int C  = in_sizes[7];          // 40
    int F  = in_sizes[2] / H;      // 512
    int n  = in_sizes[0] / F;      // 50000
    int E  = in_sizes[1] / 2;      // 1600000

    float *p_h1, *p_h2, *p_hw, *p_w, *p_inv, *p_rowsum, *p_deg, *p_degG, *p_sw, *p_dinv;
    int *p_rowptr, *p_ofs, *p_esrc;
    cudaGetSymbolAddress((void**)&p_h1, g_h1);
    cudaGetSymbolAddress((void**)&p_h2, g_h2);
    cudaGetSymbolAddress((void**)&p_hw, g_hw);
    cudaGetSymbolAddress((void**)&p_w, g_w);
    cudaGetSymbolAddress((void**)&p_inv, g_inv);
    cudaGetSymbolAddress((void**)&p_rowsum, g_rowsum);
    cudaGetSymbolAddress((void**)&p_deg, g_deg);
    cudaGetSymbolAddress((void**)&p_degG, g_degG);
    cudaGetSymbolAddress((void**)&p_sw, g_sw);
    cudaGetSymbolAddress((void**)&p_dinv, g_dinv);
    cudaGetSymbolAddress((void**)&p_rowptr, g_rowptr);
    cudaGetSymbolAddress((void**)&p_ofs, g_ofs);
    cudaGetSymbolAddress((void**)&p_esrc, g_esrc);

    const int T = 256;
    // Build CSR by dst once (edge structure identical across layers)
    zeroi_kernel<<<(n + 1 + T - 1) / T, T>>>(p_rowptr, n + 1);
    hist_kernel<<<(E + T - 1) / T, T>>>(ei, p_rowptr, E);
    scan_kernel<<<1, 1024>>>(p_rowptr, n + 1);
    copyofs_kernel<<<(n + T - 1) / T, T>>>(p_rowptr, p_ofs, n);
    scatter_kernel<<<(E + T - 1) / T, T>>>(ei, p_ofs, p_esrc, E);

    // Layer 1: x(512) -> h1(256), relu
    run_layer(x, F, W1, b1, H, n, p_hw, p_rowsum, p_deg, p_degG,
              p_inv, p_w, p_sw, p_dinv, p_rowptr, p_esrc, p_h1, true);
    // Layer 2: h1(256) -> h2(64), relu
    run_layer(p_h1, H, W2, b2, D2, n, p_hw, p_rowsum, p_deg, p_degG,
              p_inv, p_w, p_sw, p_dinv, p_rowptr, p_esrc, p_h2, true);
    // Layer 3: h2(64) -> out(40), no relu
    run_layer(p_h2, D2, W3, b3, C, n, p_hw, p_rowsum, p_deg, p_degG,
              p_inv, p_w, p_sw, p_dinv, p_rowptr, p_esrc, out, false);
    // log_softmax in place on d_out
    lsm_kernel<<<(n * 32 + 255) / 256, 256>>>(out, n, C);
}

// round 5
// speedup vs baseline: 2.0818x; 1.2156x over previous
#include <cuda_runtime.h>
#include <cuda_fp16.h>
#include <cstdint>

#define N_MAX 50000
#define E_MAX 1600000

// Scratch (device globals; allocations are forbidden)
__device__ __align__(16) float g_h1[N_MAX * 256];
__device__ __align__(16) float g_h2[N_MAX * 64];
__device__ __align__(16) float g_hw[N_MAX * 256];
__device__ __align__(16) __half g_fn[N_MAX * 512];   // normalized features, fp16
__device__ float g_w[E_MAX];        // CSR-ordered edge weights
__device__ float g_rowsum[N_MAX];
__device__ float g_deg[N_MAX];
__device__ float g_degG[N_MAX];
__device__ float g_sw[N_MAX];
__device__ float g_dinv[N_MAX];
__device__ int g_rowptr[N_MAX + 1];
__device__ int g_ofs[N_MAX];
__device__ int g_esrc[E_MAX];       // src node per CSR slot (dst-grouped)

// ---------------------------------------------------------------------------
__global__ void clear2_kernel(float* a, float* b, int n) {
    int i = blockIdx.x * blockDim.x + threadIdx.x;
    if (i < n) { a[i] = 0.f; b[i] = 0.f; }
}

__global__ void zeroi_kernel(int* a, int n) {
    int i = blockIdx.x * blockDim.x + threadIdx.x;
    if (i < n) a[i] = 0;
}

// ---------------------------------------------------------------------------
// CSR-by-dst build
__global__ void hist_kernel(const int* __restrict__ ei, int* __restrict__ rowptr, int E) {
    int e = blockIdx.x * blockDim.x + threadIdx.x;
    if (e < E) atomicAdd(&rowptr[ei[(size_t)E + e] + 1], 1);
}

// single-block inclusive scan over n ints (warp-shuffle based)
__global__ void scan_kernel(int* __restrict__ data, int n) {
    __shared__ int wsum[32];
    __shared__ int carry_s;
    int lane = threadIdx.x & 31, wid = threadIdx.x >> 5;
    if (threadIdx.x == 0) carry_s = 0;
    __syncthreads();
    for (int base = 0; base < n; base += 1024) {
        int i = base + threadIdx.x;
        int v = (i < n) ? data[i] : 0;
        int x = v;
        #pragma unroll
        for (int o = 1; o < 32; o <<= 1) {
            int t = __shfl_up_sync(0xffffffffu, x, o);
            if (lane >= o) x += t;
        }
        if (lane == 31) wsum[wid] = x;
        __syncthreads();
        if (wid == 0) {
            int ws = wsum[lane];
            #pragma unroll
            for (int o = 1; o < 32; o <<= 1) {
                int t = __shfl_up_sync(0xffffffffu, ws, o);
                if (lane >= o) ws += t;
            }
            wsum[lane] = ws;
        }
        __syncthreads();
        int offset = (wid > 0) ? wsum[wid - 1] : 0;
        int carry = carry_s;
        if (i < n) data[i] = x + offset + carry;
        __syncthreads();
        if (threadIdx.x == 1023) carry_s = carry + wsum[31];
        __syncthreads();
    }
}

__global__ void copyofs_kernel(const int* __restrict__ rowptr, int* __restrict__ ofs, int n) {
    int i = blockIdx.x * blockDim.x + threadIdx.x;
    if (i < n) ofs[i] = rowptr[i];
}

// store SRC id directly into the dst-CSR slot
__global__ void scatter_kernel(const int* __restrict__ ei, int* __restrict__ ofs,
                               int* __restrict__ esrc, int E) {
    int e = blockIdx.x * blockDim.x + threadIdx.x;
    if (e < E) {
        int pos = atomicAdd(&ofs[ei[(size_t)E + e]], 1);
        esrc[pos] = ei[e];
    }
}

// ---------------------------------------------------------------------------
// warp per node: compute inv L2 norm, write normalized fp16 row.
// VPT = float4 chunks per lane (d4 <= VPT*32)
template <int VPT>
__global__ void normfn_kernel(const float* __restrict__ h, __half* __restrict__ fn,
                              int n, int d4) {
    int node = (blockIdx.x * blockDim.x + threadIdx.x) >> 5;
    int lane = threadIdx.x & 31;
    if (node >= n) return;
    const float4* row = (const float4*)h + (size_t)node * d4;
    float4 c[VPT];
    float acc = 0.f;
    #pragma unroll
    for (int v = 0; v < VPT; v++) {
        int j = lane + v * 32;
        if (j < d4) {
            float4 t = row[j];
            c[v] = t;
            acc += t.x * t.x + t.y * t.y + t.z * t.z + t.w * t.w;
        }
    }
    #pragma unroll
    for (int o = 16; o; o >>= 1) acc += __shfl_xor_sync(0xffffffffu, acc, o);
    float iv = (acc == 0.f) ? 1.f : rsqrtf(acc);
    uint2* frow = (uint2*)(fn + (size_t)node * (d4 * 4));
    #pragma unroll
    for (int v = 0; v < VPT; v++) {
        int j = lane + v * 32;
        if (j < d4) {
            __half2 lo = __floats2half2_rn(c[v].x * iv, c[v].y * iv);
            __half2 hi = __floats2half2_rn(c[v].z * iv, c[v].w * iv);
            uint2 u;
            u.x = *(unsigned*)&lo;
            u.y = *(unsigned*)&hi;
            frow[j] = u;
        }
    }
}

// warp per dst node: dst normalized row cached in fp32 registers; per edge
// fp16 dot vs src normalized row. Writes w in CSR order; rowsum[src] atomics.
template <int VPT>
__global__ void sim_csr_kernel(const __half* __restrict__ fn,
                               const int* __restrict__ rowptr,
                               const int* __restrict__ esrc,
                               float* __restrict__ w, float* __restrict__ rowsum,
                               int n, int d4) {
    int node = (int)(((size_t)blockIdx.x * blockDim.x + threadIdx.x) >> 5);
    int lane = threadIdx.x & 31;
    if (node >= n) return;
    const uint2* f2 = (const uint2*)fn;
    const uint2* ft = f2 + (size_t)node * d4;
    float4 cached[VPT];
    #pragma unroll
    for (int v = 0; v < VPT; v++) {
        int j = lane + v * 32;
        if (j < d4) {
            uint2 u = ft[j];
            float2 lo = __half22float2(*(__half2*)&u.x);
            float2 hi = __half22float2(*(__half2*)&u.y);
            cached[v] = make_float4(lo.x, lo.y, hi.x, hi.y);
        } else cached[v] = make_float4(0.f, 0.f, 0.f, 0.f);
    }
    int p0 = rowptr[node], p1 = rowptr[node + 1];
    for (int p = p0; p < p1; p++) {
        int s = esrc[p];
        const uint2* fs = f2 + (size_t)s * d4;
        float acc = 0.f;
        #pragma unroll
        for (int v = 0; v < VPT; v++) {
            int j = lane + v * 32;
            if (j < d4) {
                uint2 u = fs[j];
                float2 lo = __half22float2(*(__half2*)&u.x);
                float2 hi = __half22float2(*(__half2*)&u.y);
                float4 b = cached[v];
                acc += lo.x * b.x + lo.y * b.y + hi.x * b.z + hi.y * b.w;
            }
        }
        #pragma unroll
        for (int o = 16; o; o >>= 1) acc += __shfl_xor_sync(0xffffffffu, acc, o);
        if (lane == 0) {
            float wv = (s != node && acc >= 0.f) ? acc : 0.f;
            w[p] = wv;
            if (wv > 0.f) atomicAdd(&rowsum[s], wv);
        }
    }
}

// thread per dst node: normalize+exp each incoming edge; deg[src] atomics;
// degG[dst] is a plain register sum.
__global__ void edge2_csr_kernel(const int* __restrict__ rowptr,
                                 const int* __restrict__ esrc,
                                 float* __restrict__ w,
                                 const float* __restrict__ rowsum,
                                 float* __restrict__ deg, float* __restrict__ degG,
                                 int n) {
    int t = blockIdx.x * blockDim.x + threadIdx.x;
    if (t >= n) return;
    int p0 = rowptr[t], p1 = rowptr[t + 1];
    float dsum = 0.f;
    for (int p = p0; p < p1; p++) {
        float wv = w[p];
        if (wv > 0.f) {
            int s = esrc[p];
            float ew = expf(wv / rowsum[s]);
            atomicAdd(&deg[s], 1.0f);
            dsum += ew;
            w[p] = ew;
        }
    }
    degG[t] = dsum;
}

__global__ void node2_kernel(const float* __restrict__ deg,
                             const float* __restrict__ degG,
                             float* __restrict__ sw, float* __restrict__ dinv,
                             int n) {
    int i = blockIdx.x * blockDim.x + threadIdx.x;
    if (i >= n) return;
    float s = expf(1.0f / (deg[i] + 1.0f));
    sw[i] = s;
    dinv[i] = rsqrtf(degG[i] + s);
}

// ---------------------------------------------------------------------------
// GEMM A: 128x128 tile, 8x8 micro, 256 threads (m % 128 == 0, k % 16 == 0)
__global__ void __launch_bounds__(256) gemm128_kernel(
        const float* __restrict__ A, const float* __restrict__ W,
        float* __restrict__ C, int n, int k, int m) {
    __shared__ float As[16][128];
    __shared__ float Ws[16][128];
    int bm = blockIdx.y * 128;
    int bn = blockIdx.x * 128;
    int tid = threadIdx.x;
    int tr = tid >> 4, tc = tid & 15;
    float acc[8][8] = {};
    for (int k0 = 0; k0 < k; k0 += 16) {
        #pragma unroll
        for (int l = 0; l < 2; l++) {
            int f = tid * 2 + l;          // 0..511
            int r = f >> 2;               // 0..127
            int c4 = (f & 3) * 4;
            int gr = bm + r;
            float4 v = make_float4(0.f, 0.f, 0.f, 0.f);
            if (gr < n) v = *(const float4*)&A[(size_t)gr * k + k0 + c4];
            As[c4 + 0][r] = v.x; As[c4 + 1][r] = v.y;
            As[c4 + 2][r] = v.z; As[c4 + 3][r] = v.w;
        }
        #pragma unroll
        for (int l = 0; l < 2; l++) {
            int f = tid * 2 + l;          // 0..511
            int r = f >> 5;               // 0..15
            int c4 = (f & 31) * 4;        // 0..124
            float4 v = *(const float4*)&W[(size_t)(k0 + r) * m + bn + c4];
            *(float4*)&Ws[r][c4] = v;
        }
        __syncthreads();
        #pragma unroll
        for (int kk = 0; kk < 16; kk++) {
            float a[8], wv[8];
            *(float4*)&a[0] = *(float4*)&As[kk][tr * 8];
            *(float4*)&a[4] = *(float4*)&As[kk][tr * 8 + 4];
            *(float4*)&wv[0] = *(float4*)&Ws[kk][tc * 8];
            *(float4*)&wv[4] = *(float4*)&Ws[kk][tc * 8 + 4];
            #pragma unroll
            for (int i = 0; i < 8; i++)
                #pragma unroll
                for (int j = 0; j < 8; j++) acc[i][j] += a[i] * wv[j];
        }
        __syncthreads();
    }
    #pragma unroll
    for (int i = 0; i < 8; i++) {
        int gr = bm + tr * 8 + i;
        if (gr >= n) continue;
        float* crow = &C[(size_t)gr * m + bn + tc * 8];
        *(float4*)&crow[0] = make_float4(acc[i][0], acc[i][1], acc[i][2], acc[i][3]);
        *(float4*)&crow[4] = make_float4(acc[i][4], acc[i][5], acc[i][6], acc[i][7]);
    }
}

// GEMM B: 128x64 tile, 8x4 micro, 256 threads (general m, k % 16 == 0)
__global__ void __launch_bounds__(256) gemm64_kernel(
        const float* __restrict__ A, const float* __restrict__ W,
        float* __restrict__ C, int n, int k, int m) {
    __shared__ float As[16][128];
    __shared__ float Ws[16][64];
    int bm = blockIdx.y * 128;
    int bn = blockIdx.x * 64;
    int tid = threadIdx.x;
    int tr = tid >> 4, tc = tid & 15;
    float acc[8][4] = {};
    for (int k0 = 0; k0 < k; k0 += 16) {
        #pragma unroll
        for (int l = 0; l < 2; l++) {
            int f = tid * 2 + l;
            int r = f >> 2;
            int c4 = (f & 3) * 4;
            int gr = bm + r;
            float4 v = make_float4(0.f, 0.f, 0.f, 0.f);
            if (gr < n) v = *(const float4*)&A[(size_t)gr * k + k0 + c4];
            As[c4 + 0][r] = v.x; As[c4 + 1][r] = v.y;
            As[c4 + 2][r] = v.z; As[c4 + 3][r] = v.w;
        }
        {
            int r = tid >> 4;
            int c4 = (tid & 15) * 4;
            int gc = bn + c4;
            const float* wrow = &W[(size_t)(k0 + r) * m];
            float4 v;
            if (gc + 3 < m) v = *(const float4*)&wrow[gc];
            else {
                v.x = (gc + 0 < m) ? wrow[gc + 0] : 0.f;
                v.y = (gc + 1 < m) ? wrow[gc + 1] : 0.f;
                v.z = (gc + 2 < m) ? wrow[gc + 2] : 0.f;
                v.w = (gc + 3 < m) ? wrow[gc + 3] : 0.f;
            }
            *(float4*)&Ws[r][c4] = v;
        }
        __syncthreads();
        #pragma unroll
        for (int kk = 0; kk < 16; kk++) {
            float a[8];
            *(float4*)&a[0] = *(float4*)&As[kk][tr * 8];
            *(float4*)&a[4] = *(float4*)&As[kk][tr * 8 + 4];
            float4 wv = *(float4*)&Ws[kk][tc * 4];
            #pragma unroll
            for (int i = 0; i < 8; i++) {
                acc[i][0] += a[i] * wv.x;
                acc[i][1] += a[i] * wv.y;
                acc[i][2] += a[i] * wv.z;
                acc[i][3] += a[i] * wv.w;
            }
        }
        __syncthreads();
    }
    #pragma unroll
    for (int i = 0; i < 8; i++) {
        int gr = bm + tr * 8 + i;
        if (gr >= n) continue;
        int gc = bn + tc * 4;
        if (gc + 3 < m) {
            *(float4*)&C[(size_t)gr * m + gc] =
                make_float4(acc[i][0], acc[i][1], acc[i][2], acc[i][3]);
        } else {
            #pragma unroll
            for (int j = 0; j < 4; j++)
                if (gc + j < m) C[(size_t)gr * m + gc + j] = acc[i][j];
        }
    }
}

// ---------------------------------------------------------------------------
// CSR aggregation, fused self-loop + bias + optional relu. warp per dst node.
template <int VPT>
__global__ void agg_csr_kernel(const int* __restrict__ rowptr,
                               const int* __restrict__ esrc,
                               const float* __restrict__ w,
                               const float* __restrict__ dinv,
                               const float* __restrict__ sw,
                               const float* __restrict__ hw,
                               const float* __restrict__ b,
                               float* __restrict__ out,
                               int n, int m4, int relu) {
    int node = (int)(((size_t)blockIdx.x * blockDim.x + threadIdx.x) >> 5);
    int lane = threadIdx.x & 31;
    if (node >= n) return;
    float4 acc[VPT];
    #pragma unroll
    for (int v = 0; v < VPT; v++) acc[v] = make_float4(0.f, 0.f, 0.f, 0.f);
    float dt = dinv[node];
    int p0 = rowptr[node], p1 = rowptr[node + 1];
    const float4* hw4 = (const float4*)hw;
    for (int p = p0; p < p1; p++) {
        float ew = w[p];
        if (ew == 0.f) continue;
        int s = esrc[p];
        float coef = ew * dinv[s] * dt;
        const float4* row = hw4 + (size_t)s * m4;
        #pragma unroll
        for (int v = 0; v < VPT; v++) {
            int j = lane + v * 32;
            if (j < m4) {
                float4 hv = row[j];
                acc[v].x += coef * hv.x; acc[v].y += coef * hv.y;
                acc[v].z += coef * hv.z; acc[v].w += coef * hv.w;
            }
        }
    }
    float self = sw[node] * dt * dt;
    const float4* srow = hw4 + (size_t)node * m4;
    float4* orow = (float4*)out + (size_t)node * m4;
    const float4* b4 = (const float4*)b;
    #pragma unroll
    for (int v = 0; v < VPT; v++) {
        int j = lane + v * 32;
        if (j < m4) {
            float4 hv = srow[j];
            float4 bv = b4[j];
            float4 r;
            r.x = acc[v].x + self * hv.x + bv.x;
            r.y = acc[v].y + self * hv.y + bv.y;
            r.z = acc[v].z + self * hv.z + bv.z;
            r.w = acc[v].w + self * hv.w + bv.w;
            if (relu) {
                r.x = fmaxf(r.x, 0.f); r.y = fmaxf(r.y, 0.f);
                r.z = fmaxf(r.z, 0.f); r.w = fmaxf(r.w, 0.f);
            }
            orow[j] = r;
        }
    }
}

// warp per row log_softmax
__global__ void lsm_kernel(float* __restrict__ out, int n, int m) {
    int row = (blockIdx.x * blockDim.x + threadIdx.x) >> 5;
    int lane = threadIdx.x & 31;
    if (row >= n) return;
    float* r = out + (size_t)row * m;
    float mx = -1e30f;
    for (int j = lane; j < m; j += 32) mx = fmaxf(mx, r[j]);
    #pragma unroll
    for (int o = 16; o; o >>= 1) mx = fmaxf(mx, __shfl_xor_sync(0xffffffffu, mx, o));
    float se = 0.f;
    for (int j = lane; j < m; j += 32) se += expf(r[j] - mx);
    #pragma unroll
    for (int o = 16; o; o >>= 1) se += __shfl_xor_sync(0xffffffffu, se, o);
    float l = mx + logf(se);
    for (int j = lane; j < m; j += 32) r[j] -= l;
}

// ---------------------------------------------------------------------------
static void run_layer(const float* h, int d, const float* W, const float* b,
                      int dout, int n,
                      float* hw, float* rowsum, float* deg, float* degG,
                      __half* fn, float* w, float* sw, float* dinv,
                      const int* rowptr, const int* esrc,
                      float* out, bool do_relu) {
    const int T = 256;
    int d4 = d >> 2;
    clear2_kernel<<<(n + T - 1) / T, T>>>(rowsum, deg, n);
    int wb = (int)(((size_t)n * 32 + T - 1) / T);
    if (d4 > 64)       normfn_kernel<4><<<wb, T>>>(h, fn, n, d4);
    else if (d4 > 32)  normfn_kernel<2><<<wb, T>>>(h, fn, n, d4);
    else               normfn_kernel<1><<<wb, T>>>(h, fn, n, d4);
    if (d4 > 64)       sim_csr_kernel<4><<<wb, T>>>(fn, rowptr, esrc, w, rowsum, n, d4);
    else if (d4 > 32)  sim_csr_kernel<2><<<wb, T>>>(fn, rowptr, esrc, w, rowsum, n, d4);
    else               sim_csr_kernel<1><<<wb, T>>>(fn, rowptr, esrc, w, rowsum, n, d4);
    edge2_csr_kernel<<<(n + T - 1) / T, T>>>(rowptr, esrc, w, rowsum, deg, degG, n);
    node2_kernel<<<(n + T - 1) / T, T>>>(deg, degG, sw, dinv, n);
    if ((dout & 127) == 0) {
        dim3 gg(dout / 128, (n + 127) / 128);
        gemm128_kernel<<<gg, 256>>>(h, W, hw, n, d, dout);
    } else {
        dim3 gg((dout + 63) / 64, (n + 127) / 128);
        gemm64_kernel<<<gg, 256>>>(h, W, hw, n, d, dout);
    }
    int m4 = dout >> 2;
    if (m4 > 32)
        agg_csr_kernel<2><<<wb, T>>>(rowptr, esrc, w, dinv, sw, hw, b, out,
                                     n, m4, do_relu ? 1 : 0);
    else
        agg_csr_kernel<1><<<wb, T>>>(rowptr, esrc, w, dinv, sw, hw, b, out,
                                     n, m4, do_relu ? 1 : 0);
}

extern "C" void kernel_launch(void* const* d_in, const int* in_sizes, int n_in,
                              void* d_out, int out_size) {
    const float* x = (const float*)d_in[0];
    const int* ei = (const int*)d_in[1];     // int32 (JAX default)
    const float* W1 = (const float*)d_in[2];
    const float* b1 = (const float*)d_in[3];
    const float* W2 = (const float*)d_in[4];
    const float* b2 = (const float*)d_in[5];
    const float* W3 = (const float*)d_in[6];
    const float* b3 = (const float*)d_in[7];
    float* out = (float*)d_out;

    int H  = in_sizes[3];          // 256
    int D2 = in_sizes[5];          // 64
    int C  = in_sizes[7];          // 40
    int F  = in_sizes[2] / H;      // 512
    int n  = in_sizes[0] / F;      // 50000
    int E  = in_sizes[1] / 2;      // 1600000

    float *p_h1, *p_h2, *p_hw, *p_w, *p_rowsum, *p_deg, *p_degG, *p_sw, *p_dinv;
    __half* p_fn;
    int *p_rowptr, *p_ofs, *p_esrc;
    cudaGetSymbolAddress((void**)&p_h1, g_h1);
    cudaGetSymbolAddress((void**)&p_h2, g_h2);
    cudaGetSymbolAddress((void**)&p_hw, g_hw);
    cudaGetSymbolAddress((void**)&p_fn, g_fn);
    cudaGetSymbolAddress((void**)&p_w, g_w);
    cudaGetSymbolAddress((void**)&p_rowsum, g_rowsum);
    cudaGetSymbolAddress((void**)&p_deg, g_deg);
    cudaGetSymbolAddress((void**)&p_degG, g_degG);
    cudaGetSymbolAddress((void**)&p_sw, g_sw);
    cudaGetSymbolAddress((void**)&p_dinv, g_dinv);
    cudaGetSymbolAddress((void**)&p_rowptr, g_rowptr);
    cudaGetSymbolAddress((void**)&p_ofs, g_ofs);
    cudaGetSymbolAddress((void**)&p_esrc, g_esrc);

    const int T = 256;
    // Build CSR by dst once (edge structure identical across layers)
    zeroi_kernel<<<(n + 1 + T - 1) / T, T>>>(p_rowptr, n + 1);
    hist_kernel<<<(E + T - 1) / T, T>>>(ei, p_rowptr, E);
    scan_kernel<<<1, 1024>>>(p_rowptr, n + 1);
    copyofs_kernel<<<(n + T - 1) / T, T>>>(p_rowptr, p_ofs, n);
    scatter_kernel<<<(E + T - 1) / T, T>>>(ei, p_ofs, p_esrc, E);

    // Layer 1: x(512) -> h1(256), relu
    run_layer(x, F, W1, b1, H, n, p_hw, p_rowsum, p_deg, p_degG,
              p_fn, p_w, p_sw, p_dinv, p_rowptr, p_esrc, p_h1, true);
    // Layer 2: h1(256) -> h2(64), relu
    run_layer(p_h1, H, W2, b2, D2, n, p_hw, p_rowsum, p_deg, p_degG,
              p_fn, p_w, p_sw, p_dinv, p_rowptr, p_esrc, p_h2, true);
    // Layer 3: h2(64) -> out(40), no relu
    run_layer(p_h2, D2, W3, b3, C, n, p_hw, p_rowsum, p_deg, p_degG,
              p_fn, p_w, p_sw, p_dinv, p_rowptr, p_esrc, out, false);
    // log_softmax in place on d_out
    lsm_kernel<<<(n * 32 + 255) / 256, 256>>>(out, n, C);
}

// round 7
// speedup vs baseline: 2.1116x; 1.0143x over previous
#include <cuda_runtime.h>
#include <cuda_fp16.h>
#include <mma.h>
#include <cstdint>

using namespace nvcuda;

#define N_MAX 50000
#define N_PAD (N_MAX + 64)
#define E_MAX 1600000

// Scratch (device globals; allocations are forbidden)
__device__ __align__(16) float g_h1[N_MAX * 256];
__device__ __align__(16) float g_h2[N_MAX * 64];
__device__ __align__(16) float g_hw[N_PAD * 256];      // padded for wmma OOB rows
__device__ __align__(16) __half g_fn[(size_t)N_PAD * 512]; // normalized features fp16 (padded)
__device__ __align__(16) __half g_wh[512 * 256];       // fp16 weights
__device__ float g_w[E_MAX];        // CSR-ordered edge weights
__device__ float g_hscale[N_MAX];   // row norms (h = fn * hscale)
__device__ float g_rowsum[N_MAX];
__device__ float g_deg[N_MAX];
__device__ float g_degG[N_MAX];
__device__ float g_sw[N_MAX];
__device__ float g_dinv[N_MAX];
__device__ int g_rowptr[N_MAX + 1];
__device__ int g_ofs[N_MAX];
__device__ int g_esrc[E_MAX];       // src node per CSR slot (dst-grouped)

// ---------------------------------------------------------------------------
__global__ void clear2_kernel(float* a, float* b, int n) {
    int i = blockIdx.x * blockDim.x + threadIdx.x;
    if (i < n) { a[i] = 0.f; b[i] = 0.f; }
}

__global__ void zeroi_kernel(int* a, int n) {
    int i = blockIdx.x * blockDim.x + threadIdx.x;
    if (i < n) a[i] = 0;
}

__global__ void zeroh_kernel(__half* a, int n) {
    int i = blockIdx.x * blockDim.x + threadIdx.x;
    if (i < n) a[i] = __float2half(0.f);
}

// ---------------------------------------------------------------------------
// CSR-by-dst build
__global__ void hist_kernel(const int* __restrict__ ei, int* __restrict__ rowptr, int E) {
    int e = blockIdx.x * blockDim.x + threadIdx.x;
    if (e < E) atomicAdd(&rowptr[ei[(size_t)E + e] + 1], 1);
}

__global__ void scan_kernel(int* __restrict__ data, int n) {
    __shared__ int wsum[32];
    __shared__ int carry_s;
    int lane = threadIdx.x & 31, wid = threadIdx.x >> 5;
    if (threadIdx.x == 0) carry_s = 0;
    __syncthreads();
    for (int base = 0; base < n; base += 1024) {
        int i = base + threadIdx.x;
        int v = (i < n) ? data[i] : 0;
        int x = v;
        #pragma unroll
        for (int o = 1; o < 32; o <<= 1) {
            int t = __shfl_up_sync(0xffffffffu, x, o);
            if (lane >= o) x += t;
        }
        if (lane == 31) wsum[wid] = x;
        __syncthreads();
        if (wid == 0) {
            int ws = wsum[lane];
            #pragma unroll
            for (int o = 1; o < 32; o <<= 1) {
                int t = __shfl_up_sync(0xffffffffu, ws, o);
                if (lane >= o) ws += t;
            }
            wsum[lane] = ws;
        }
        __syncthreads();
        int offset = (wid > 0) ? wsum[wid - 1] : 0;
        int carry = carry_s;
        if (i < n) data[i] = x + offset + carry;
        __syncthreads();
        if (threadIdx.x == 1023) carry_s = carry + wsum[31];
        __syncthreads();
    }
}

__global__ void copyofs_kernel(const int* __restrict__ rowptr, int* __restrict__ ofs, int n) {
    int i = blockIdx.x * blockDim.x + threadIdx.x;
    if (i < n) ofs[i] = rowptr[i];
}

__global__ void scatter_kernel(const int* __restrict__ ei, int* __restrict__ ofs,
                               int* __restrict__ esrc, int E) {
    int e = blockIdx.x * blockDim.x + threadIdx.x;
    if (e < E) {
        int pos = atomicAdd(&ofs[ei[(size_t)E + e]], 1);
        esrc[pos] = ei[e];
    }
}

// ---------------------------------------------------------------------------
// warp per node: inv L2 norm; write normalized fp16 row + row norm (hscale).
template <int VPT>
__global__ void normfn_kernel(const float* __restrict__ h, __half* __restrict__ fn,
                              float* __restrict__ hscale, int n, int d4) {
    int node = (blockIdx.x * blockDim.x + threadIdx.x) >> 5;
    int lane = threadIdx.x & 31;
    if (node >= n) return;
    const float4* row = (const float4*)h + (size_t)node * d4;
    float4 c[VPT];
    float acc = 0.f;
    #pragma unroll
    for (int v = 0; v < VPT; v++) {
        int j = lane + v * 32;
        if (j < d4) {
            float4 t = row[j];
            c[v] = t;
            acc += t.x * t.x + t.y * t.y + t.z * t.z + t.w * t.w;
        }
    }
    #pragma unroll
    for (int o = 16; o; o >>= 1) acc += __shfl_xor_sync(0xffffffffu, acc, o);
    float iv = (acc == 0.f) ? 1.f : rsqrtf(acc);
    if (lane == 0) hscale[node] = (acc == 0.f) ? 1.f : sqrtf(acc);
    uint2* frow = (uint2*)(fn + (size_t)node * (d4 * 4));
    #pragma unroll
    for (int v = 0; v < VPT; v++) {
        int j = lane + v * 32;
        if (j < d4) {
            __half2 lo = __floats2half2_rn(c[v].x * iv, c[v].y * iv);
            __half2 hi = __floats2half2_rn(c[v].z * iv, c[v].w * iv);
            uint2 u;
            u.x = *(unsigned*)&lo;
            u.y = *(unsigned*)&hi;
            frow[j] = u;
        }
    }
}

// warp per dst node: fp16 dot vs cached dst row; w in CSR order; rowsum atomics
template <int VPT>
__global__ void sim_csr_kernel(const __half* __restrict__ fn,
                               const int* __restrict__ rowptr,
                               const int* __restrict__ esrc,
                               float* __restrict__ w, float* __restrict__ rowsum,
                               int n, int d4) {
    int node = (int)(((size_t)blockIdx.x * blockDim.x + threadIdx.x) >> 5);
    int lane = threadIdx.x & 31;
    if (node >= n) return;
    const uint2* f2 = (const uint2*)fn;
    const uint2* ft = f2 + (size_t)node * d4;
    float4 cached[VPT];
    #pragma unroll
    for (int v = 0; v < VPT; v++) {
        int j = lane + v * 32;
        if (j < d4) {
            uint2 u = ft[j];
            float2 lo = __half22float2(*(__half2*)&u.x);
            float2 hi = __half22float2(*(__half2*)&u.y);
            cached[v] = make_float4(lo.x, lo.y, hi.x, hi.y);
        } else cached[v] = make_float4(0.f, 0.f, 0.f, 0.f);
    }
    int p0 = rowptr[node], p1 = rowptr[node + 1];
    for (int p = p0; p < p1; p++) {
        int s = esrc[p];
        const uint2* fs = f2 + (size_t)s * d4;
        float acc = 0.f;
        #pragma unroll
        for (int v = 0; v < VPT; v++) {
            int j = lane + v * 32;
            if (j < d4) {
                uint2 u = fs[j];
                float2 lo = __half22float2(*(__half2*)&u.x);
                float2 hi = __half22float2(*(__half2*)&u.y);
                float4 b = cached[v];
                acc += lo.x * b.x + lo.y * b.y + hi.x * b.z + hi.y * b.w;
            }
        }
        #pragma unroll
        for (int o = 16; o; o >>= 1) acc += __shfl_xor_sync(0xffffffffu, acc, o);
        if (lane == 0) {
            float wv = (s != node && acc >= 0.f) ? acc : 0.f;
            w[p] = wv;
            if (wv > 0.f) atomicAdd(&rowsum[s], wv);
        }
    }
}

__global__ void edge2_csr_kernel(const int* __restrict__ rowptr,
                                 const int* __restrict__ esrc,
                                 float* __restrict__ w,
                                 const float* __restrict__ rowsum,
                                 float* __restrict__ deg, float* __restrict__ degG,
                                 int n) {
    int t = blockIdx.x * blockDim.x + threadIdx.x;
    if (t >= n) return;
    int p0 = rowptr[t], p1 = rowptr[t + 1];
    float dsum = 0.f;
    for (int p = p0; p < p1; p++) {
        float wv = w[p];
        if (wv > 0.f) {
            int s = esrc[p];
            float ew = expf(wv / rowsum[s]);
            atomicAdd(&deg[s], 1.0f);
            dsum += ew;
            w[p] = ew;
        }
    }
    degG[t] = dsum;
}

__global__ void node2_kernel(const float* __restrict__ deg,
                             const float* __restrict__ degG,
                             float* __restrict__ sw, float* __restrict__ dinv,
                             int n) {
    int i = blockIdx.x * blockDim.x + threadIdx.x;
    if (i >= n) return;
    float s = expf(1.0f / (deg[i] + 1.0f));
    sw[i] = s;
    dinv[i] = rsqrtf(degG[i] + s);
}

// ---------------------------------------------------------------------------
// W (fp32) -> fp16
__global__ void convw_kernel(const float* __restrict__ W, __half* __restrict__ Wh, int total) {
    int i = blockIdx.x * blockDim.x + threadIdx.x;
    if (i < total) Wh[i] = __float2half(W[i]);
}

// HMMA GEMM: C[n_pad x m] = A(fp16)[n_pad x k] @ Wh[k x m], fp32 accum.
// Block = 256 threads (8 warps, 4 row x 2 col), tile 64 x m. FC = m/32.
template <int FC>
__global__ void __launch_bounds__(256) hmma_gemm_kernel(
        const __half* __restrict__ A, const __half* __restrict__ Wh,
        float* __restrict__ C, int k, int m) {
    __shared__ __align__(16) __half As[64 * 16];
    __shared__ __align__(16) __half Ws[16 * 256];
    int bm = blockIdx.x * 64;
    int tid = threadIdx.x;
    int wid = tid >> 5;
    int wr = wid >> 1, wc = wid & 1;
    wmma::fragment<wmma::accumulator, 16, 16, 16, float> acc[FC];
    #pragma unroll
    for (int f = 0; f < FC; f++) wmma::fill_fragment(acc[f], 0.f);
    int mdiv8 = m >> 3;
    for (int k0 = 0; k0 < k; k0 += 16) {
        if (tid < 128) {
            int r = tid >> 1, seg = (tid & 1) * 8;
            *(float4*)&As[r * 16 + seg] =
                *(const float4*)&A[(size_t)(bm + r) * k + k0 + seg];
        }
        for (int f = tid; f < 2 * m; f += 256) {
            int r = f / mdiv8, c = (f % mdiv8) * 8;
            *(float4*)&Ws[r * m + c] = *(const float4*)&Wh[(size_t)(k0 + r) * m + c];
        }
        __syncthreads();
        wmma::fragment<wmma::matrix_a, 16, 16, 16, __half, wmma::row_major> fa;
        wmma::load_matrix_sync(fa, &As[wr * 16 * 16], 16);
        #pragma unroll
        for (int f = 0; f < FC; f++) {
            wmma::fragment<wmma::matrix_b, 16, 16, 16, __half, wmma::row_major> fb;
            wmma::load_matrix_sync(fb, &Ws[(wc * FC + f) * 16], m);
            wmma::mma_sync(acc[f], fa, fb, acc[f]);
        }
        __syncthreads();
    }
    #pragma unroll
    for (int f = 0; f < FC; f++)
        wmma::store_matrix_sync(&C[(size_t)(bm + wr * 16) * m + (wc * FC + f) * 16],
                                acc[f], m, wmma::mem_row_major);
}

// ---------------------------------------------------------------------------
// SIMT GEMM (layer 3): 128x64 tile, 8x4 micro (general m, k % 16 == 0)
__global__ void __launch_bounds__(256) gemm64_kernel(
        const float* __restrict__ A, const float* __restrict__ W,
        float* __restrict__ C, int n, int k, int m) {
    __shared__ float As[16][128];
    __shared__ float Ws[16][64];
    int bm = blockIdx.y * 128;
    int bn = blockIdx.x * 64;
    int tid = threadIdx.x;
    int tr = tid >> 4, tc = tid & 15;
    float acc[8][4] = {};
    for (int k0 = 0; k0 < k; k0 += 16) {
        #pragma unroll
        for (int l = 0; l < 2; l++) {
            int f = tid * 2 + l;
            int r = f >> 2;
            int c4 = (f & 3) * 4;
            int gr = bm + r;
            float4 v = make_float4(0.f, 0.f, 0.f, 0.f);
            if (gr < n) v = *(const float4*)&A[(size_t)gr * k + k0 + c4];
            As[c4 + 0][r] = v.x; As[c4 + 1][r] = v.y;
            As[c4 + 2][r] = v.z; As[c4 + 3][r] = v.w;
        }
        {
            int r = tid >> 4;
            int c4 = (tid & 15) * 4;
            int gc = bn + c4;
            const float* wrow = &W[(size_t)(k0 + r) * m];
            float4 v;
            if (gc + 3 < m) v = *(const float4*)&wrow[gc];
            else {
                v.x = (gc + 0 < m) ? wrow[gc + 0] : 0.f;
                v.y = (gc + 1 < m) ? wrow[gc + 1] : 0.f;
                v.z = (gc + 2 < m) ? wrow[gc + 2] : 0.f;
                v.w = (gc + 3 < m) ? wrow[gc + 3] : 0.f;
            }
            *(float4*)&Ws[r][c4] = v;
        }
        __syncthreads();
        #pragma unroll
        for (int kk = 0; kk < 16; kk++) {
            float a[8];
            *(float4*)&a[0] = *(float4*)&As[kk][tr * 8];
            *(float4*)&a[4] = *(float4*)&As[kk][tr * 8 + 4];
            float4 wv = *(float4*)&Ws[kk][tc * 4];
            #pragma unroll
            for (int i = 0; i < 8; i++) {
                acc[i][0] += a[i] * wv.x;
                acc[i][1] += a[i] * wv.y;
                acc[i][2] += a[i] * wv.z;
                acc[i][3] += a[i] * wv.w;
            }
        }
        __syncthreads();
    }
    #pragma unroll
    for (int i = 0; i < 8; i++) {
        int gr = bm + tr * 8 + i;
        if (gr >= n) continue;
        int gc = bn + tc * 4;
        if (gc + 3 < m) {
            *(float4*)&C[(size_t)gr * m + gc] =
                make_float4(acc[i][0], acc[i][1], acc[i][2], acc[i][3]);
        } else {
            #pragma unroll
            for (int j = 0; j < 4; j++)
                if (gc + j < m) C[(size_t)gr * m + gc + j] = acc[i][j];
        }
    }
}

// ---------------------------------------------------------------------------
// CSR aggregation: fused self-loop + bias + optional relu + per-row hscale.
template <int VPT>
__global__ void agg_csr_kernel(const int* __restrict__ rowptr,
                               const int* __restrict__ esrc,
                               const float* __restrict__ w,
                               const float* __restrict__ dinv,
                               const float* __restrict__ sw,
                               const float* __restrict__ hw,
                               const float* __restrict__ b,
                               const float* __restrict__ hscale,
                               float* __restrict__ out,
                               int n, int m4, int relu) {
    int node = (int)(((size_t)blockIdx.x * blockDim.x + threadIdx.x) >> 5);
    int lane = threadIdx.x & 31;
    if (node >= n) return;
    float4 acc[VPT];
    #pragma unroll
    for (int v = 0; v < VPT; v++) acc[v] = make_float4(0.f, 0.f, 0.f, 0.f);
    float dt = dinv[node];
    int p0 = rowptr[node], p1 = rowptr[node + 1];
    const float4* hw4 = (const float4*)hw;
    for (int p = p0; p < p1; p++) {
        float ew = w[p];
        if (ew == 0.f) continue;
        int s = esrc[p];
        float sc = hscale ? hscale[s] : 1.f;
        float coef = ew * dinv[s] * dt * sc;
        const float4* row = hw4 + (size_t)s * m4;
        #pragma unroll
        for (int v = 0; v < VPT; v++) {
            int j = lane + v * 32;
            if (j < m4) {
                float4 hv = row[j];
                acc[v].x += coef * hv.x; acc[v].y += coef * hv.y;
                acc[v].z += coef * hv.z; acc[v].w += coef * hv.w;
            }
        }
    }
    float selfsc = hscale ? hscale[node] : 1.f;
    float self = sw[node] * dt * dt * selfsc;
    const float4* srow = hw4 + (size_t)node * m4;
    float4* orow = (float4*)out + (size_t)node * m4;
    const float4* b4 = (const float4*)b;
    #pragma unroll
    for (int v = 0; v < VPT; v++) {
        int j = lane + v * 32;
        if (j < m4) {
            float4 hv = srow[j];
            float4 bv = b4[j];
            float4 r;
            r.x = acc[v].x + self * hv.x + bv.x;
            r.y = acc[v].y + self * hv.y + bv.y;
            r.z = acc[v].z + self * hv.z + bv.z;
            r.w = acc[v].w + self * hv.w + bv.w;
            if (relu) {
                r.x = fmaxf(r.x, 0.f); r.y = fmaxf(r.y, 0.f);
                r.z = fmaxf(r.z, 0.f); r.w = fmaxf(r.w, 0.f);
            }
            orow[j] = r;
        }
    }
}

// warp per row log_softmax
__global__ void lsm_kernel(float* __restrict__ out, int n, int m) {
    int row = (blockIdx.x * blockDim.x + threadIdx.x) >> 5;
    int lane = threadIdx.x & 31;
    if (row >= n) return;
    float* r = out + (size_t)row * m;
    float mx = -1e30f;
    for (int j = lane; j < m; j += 32) mx = fmaxf(mx, r[j]);
    #pragma unroll
    for (int o = 16; o; o >>= 1) mx = fmaxf(mx, __shfl_xor_sync(0xffffffffu, mx, o));
    float se = 0.f;
    for (int j = lane; j < m; j += 32) se += expf(r[j] - mx);
    #pragma unroll
    for (int o = 16; o; o >>= 1) se += __shfl_xor_sync(0xffffffffu, se, o);
    float l = mx + logf(se);
    for (int j = lane; j < m; j += 32) r[j] -= l;
}

// ---------------------------------------------------------------------------
static void run_layer(const float* h, int d, const float* W, const float* b,
                      int dout, int n,
                      float* hw, float* rowsum, float* deg, float* degG,
                      __half* fn, __half* wh, float* hscale,
                      float* w, float* sw, float* dinv,
                      const int* rowptr, const int* esrc,
                      float* out, bool do_relu, bool use_hmma) {
    const int T = 256;
    int d4 = d >> 2;
    clear2_kernel<<<(n + T - 1) / T, T>>>(rowsum, deg, n);
    int wb = (int)(((size_t)n * 32 + T - 1) / T);
    if (d4 > 64)       normfn_kernel<4><<<wb, T>>>(h, fn, hscale, n, d4);
    else if (d4 > 32)  normfn_kernel<2><<<wb, T>>>(h, fn, hscale, n, d4);
    else               normfn_kernel<1><<<wb, T>>>(h, fn, hscale, n, d4);
    if (d4 > 64)       sim_csr_kernel<4><<<wb, T>>>(fn, rowptr, esrc, w, rowsum, n, d4);
    else if (d4 > 32)  sim_csr_kernel<2><<<wb, T>>>(fn, rowptr, esrc, w, rowsum, n, d4);
    else               sim_csr_kernel<1><<<wb, T>>>(fn, rowptr, esrc, w, rowsum, n, d4);
    edge2_csr_kernel<<<(n + T - 1) / T, T>>>(rowptr, esrc, w, rowsum, deg, degG, n);
    node2_kernel<<<(n + T - 1) / T, T>>>(deg, degG, sw, dinv, n);
    const float* agg_hscale = nullptr;
    if (use_hmma) {
        convw_kernel<<<(d * dout + T - 1) / T, T>>>(W, wh, d * dout);
        int gb = (n + 63) / 64;
        if (dout == 256)     hmma_gemm_kernel<8><<<gb, 256>>>(fn, wh, hw, d, dout);
        else                 hmma_gemm_kernel<2><<<gb, 256>>>(fn, wh, hw, d, dout);
        agg_hscale = hscale;
    } else {
        dim3 gg((dout + 63) / 64, (n + 127) / 128);
        gemm64_kernel<<<gg, 256>>>(h, W, hw, n, d, dout);
    }
    int m4 = dout >> 2;
    if (m4 > 32)
        agg_csr_kernel<2><<<wb, T>>>(rowptr, esrc, w, dinv, sw, hw, b, agg_hscale,
                                     out, n, m4, do_relu ? 1 : 0);
    else
        agg_csr_kernel<1><<<wb, T>>>(rowptr, esrc, w, dinv, sw, hw, b, agg_hscale,
                                     out, n, m4, do_relu ? 1 : 0);
}

extern "C" void kernel_launch(void* const* d_in, const int* in_sizes, int n_in,
                              void* d_out, int out_size) {
    const float* x = (const float*)d_in[0];
    const int* ei = (const int*)d_in[1];     // int32 (JAX default)
    const float* W1 = (const float*)d_in[2];
    const float* b1 = (const float*)d_in[3];
    const float* W2 = (const float*)d_in[4];
    const float* b2 = (const float*)d_in[5];
    const float* W3 = (const float*)d_in[6];
    const float* b3 = (const float*)d_in[7];
    float* out = (float*)d_out;

    int H  = in_sizes[3];          // 256
    int D2 = in_sizes[5];          // 64
    int C  = in_sizes[7];          // 40
    int F  = in_sizes[2] / H;      // 512
    int n  = in_sizes[0] / F;      // 50000
    int E  = in_sizes[1] / 2;      // 1600000

    float *p_h1, *p_h2, *p_hw, *p_w, *p_hscale, *p_rowsum, *p_deg, *p_degG, *p_sw, *p_dinv;
    __half *p_fn, *p_wh;
    int *p_rowptr, *p_ofs, *p_esrc;
    cudaGetSymbolAddress((void**)&p_h1, g_h1);
    cudaGetSymbolAddress((void**)&p_h2, g_h2);
    cudaGetSymbolAddress((void**)&p_hw, g_hw);
    cudaGetSymbolAddress((void**)&p_fn, g_fn);
    cudaGetSymbolAddress((void**)&p_wh, g_wh);
    cudaGetSymbolAddress((void**)&p_w, g_w);
    cudaGetSymbolAddress((void**)&p_hscale, g_hscale);
    cudaGetSymbolAddress((void**)&p_rowsum, g_rowsum);
    cudaGetSymbolAddress((void**)&p_deg, g_deg);
    cudaGetSymbolAddress((void**)&p_degG, g_degG);
    cudaGetSymbolAddress((void**)&p_sw, g_sw);
    cudaGetSymbolAddress((void**)&p_dinv, g_dinv);
    cudaGetSymbolAddress((void**)&p_rowptr, g_rowptr);
    cudaGetSymbolAddress((void**)&p_ofs, g_ofs);
    cudaGetSymbolAddress((void**)&p_esrc, g_esrc);

    const int T = 256;
    // Zero the padded tail of fn once (so padded wmma A-rows are clean zeros)
    {
        int tail = 64 * 512;
        zeroh_kernel<<<(tail + T - 1) / T, T>>>(p_fn + (size_t)N_MAX * 512, tail);
    }
    // Build CSR by dst once (edge structure identical across layers)
    zeroi_kernel<<<(n + 1 + T - 1) / T, T>>>(p_rowptr, n + 1);
    hist_kernel<<<(E + T - 1) / T, T>>>(ei, p_rowptr, E);
    scan_kernel<<<1, 1024>>>(p_rowptr, n + 1);
    copyofs_kernel<<<(n + T - 1) / T, T>>>(p_rowptr, p_ofs, n);
    scatter_kernel<<<(E + T - 1) / T, T>>>(ei, p_ofs, p_esrc, E);

    // Layer 1: x(512) -> h1(256), relu, HMMA
    run_layer(x, F, W1, b1, H, n, p_hw, p_rowsum, p_deg, p_degG,
              p_fn, p_wh, p_hscale, p_w, p_sw, p_dinv, p_rowptr, p_esrc,
              p_h1, true, true);
    // Layer 2: h1(256) -> h2(64), relu, HMMA
    run_layer(p_h1, H, W2, b2, D2, n, p_hw, p_rowsum, p_deg, p_degG,
              p_fn, p_wh, p_hscale, p_w, p_sw, p_dinv, p_rowptr, p_esrc,
              p_h2, true, true);
    // Layer 3: h2(64) -> out(40), no relu, SIMT (m=40)
    run_layer(p_h2, D2, W3, b3, C, n, p_hw, p_rowsum, p_deg, p_degG,
              p_fn, p_wh, p_hscale, p_w, p_sw, p_dinv, p_rowptr, p_esrc,
              out, false, false);
    // log_softmax in place on d_out
    lsm_kernel<<<(n * 32 + 255) / 256, 256>>>(out, n, C);
}

// round 8
// speedup vs baseline: 2.5918x; 1.2274x over previous
#include <cuda_runtime.h>
#include <cuda_fp16.h>
#include <mma.h>
#include <cstdint>

using namespace nvcuda;

#define N_MAX 50000
#define N_PAD (N_MAX + 128)
#define E_MAX 1600000

// Scratch (device globals; allocations are forbidden)
__device__ __align__(16) float g_h1[N_MAX * 256];
__device__ __align__(16) float g_h2[N_MAX * 64];
__device__ __align__(16) float g_hw[(size_t)N_PAD * 256];   // padded for wmma OOB rows
__device__ __align__(16) __half g_fn[(size_t)N_PAD * 512];  // normalized features fp16 (padded)
__device__ __align__(16) __half g_wh[512 * 256];            // fp16 weights
__device__ float g_w[E_MAX];        // CSR-ordered edge weights
__device__ float g_hscale[N_MAX];   // row norms (h = fn * hscale)
__device__ float g_rowsum[N_MAX];
__device__ float g_deg[N_MAX];
__device__ float g_degG[N_MAX];
__device__ float g_sw[N_MAX];
__device__ float g_dinv[N_MAX];
__device__ int g_rowptr[N_MAX + 1];
__device__ int g_ofs[N_MAX];
__device__ int g_esrc[E_MAX];       // src node per CSR slot (dst-grouped)
__device__ int g_bsum[64];          // scan block sums

// ---------------------------------------------------------------------------
__global__ void clear2_kernel(float* a, float* b, int n) {
    int i = blockIdx.x * blockDim.x + threadIdx.x;
    if (i < n) { a[i] = 0.f; b[i] = 0.f; }
}

__global__ void zeroi_kernel(int* a, int n) {
    int i = blockIdx.x * blockDim.x + threadIdx.x;
    if (i < n) a[i] = 0;
}

__global__ void zeroh_kernel(__half* a, int n) {
    int i = blockIdx.x * blockDim.x + threadIdx.x;
    if (i < n) a[i] = __float2half(0.f);
}

// ---------------------------------------------------------------------------
// CSR-by-dst build
__global__ void hist_kernel(const int* __restrict__ ei, int* __restrict__ rowptr, int E) {
    int e = blockIdx.x * blockDim.x + threadIdx.x;
    if (e < E) atomicAdd(&rowptr[ei[(size_t)E + e] + 1], 1);
}

// Parallel scan: stage 1 — per-block inclusive scan of 4096 elems (1024 thr x 4)
#define SCHUNK 4096
__global__ void scan1_kernel(int* __restrict__ data, int n, int* __restrict__ bsum) {
    __shared__ int ws[32];
    int tid = threadIdx.x, lane = tid & 31, w = tid >> 5;
    int base = blockIdx.x * SCHUNK;
    int idx = base + tid * 4;
    int v0 = (idx + 0 < n) ? data[idx + 0] : 0;
    int v1 = (idx + 1 < n) ? data[idx + 1] : 0;
    int v2 = (idx + 2 < n) ? data[idx + 2] : 0;
    int v3 = (idx + 3 < n) ? data[idx + 3] : 0;
    int e1 = v0 + v1, e2 = e1 + v2, e3 = e2 + v3;
    int x = e3;
    #pragma unroll
    for (int o = 1; o < 32; o <<= 1) {
        int t = __shfl_up_sync(0xffffffffu, x, o);
        if (lane >= o) x += t;
    }
    int wexcl = x - e3;
    if (lane == 31) ws[w] = x;
    __syncthreads();
    if (w == 0) {
        int s = ws[lane];
        #pragma unroll
        for (int o = 1; o < 32; o <<= 1) {
            int t = __shfl_up_sync(0xffffffffu, s, o);
            if (lane >= o) s += t;
        }
        ws[lane] = s;
    }
    __syncthreads();
    int off = ((w > 0) ? ws[w - 1] : 0) + wexcl;
    if (idx + 0 < n) data[idx + 0] = v0 + off;
    if (idx + 1 < n) data[idx + 1] = e1 + off;
    if (idx + 2 < n) data[idx + 2] = e2 + off;
    if (idx + 3 < n) data[idx + 3] = e3 + off;
    if (tid == 0) bsum[blockIdx.x] = ws[31];
}

// stage 2 — single warp inclusive scan of block sums (nb <= 64)
__global__ void scan2_kernel(int* __restrict__ bsum, int nb) {
    int lane = threadIdx.x;
    int carry = 0;
    for (int base = 0; base < nb; base += 32) {
        int i = base + lane;
        int v = (i < nb) ? bsum[i] : 0;
        int x = v;
        #pragma unroll
        for (int o = 1; o < 32; o <<= 1) {
            int t = __shfl_up_sync(0xffffffffu, x, o);
            if (lane >= o) x += t;
        }
        if (i < nb) bsum[i] = x + carry;
        carry += __shfl_sync(0xffffffffu, x, 31);
    }
}

// stage 3 — add previous-block inclusive sums
__global__ void scan3_kernel(int* __restrict__ data, int n, const int* __restrict__ bsum) {
    int b = blockIdx.x + 1;                 // blocks 1..nb-1
    int base = b * SCHUNK;
    int add = bsum[b - 1];
    int idx = base + threadIdx.x * 4;
    #pragma unroll
    for (int j = 0; j < 4; j++)
        if (idx + j < n) data[idx + j] += add;
}

__global__ void copyofs_kernel(const int* __restrict__ rowptr, int* __restrict__ ofs, int n) {
    int i = blockIdx.x * blockDim.x + threadIdx.x;
    if (i < n) ofs[i] = rowptr[i];
}

__global__ void scatter_kernel(const int* __restrict__ ei, int* __restrict__ ofs,
                               int* __restrict__ esrc, int E) {
    int e = blockIdx.x * blockDim.x + threadIdx.x;
    if (e < E) {
        int pos = atomicAdd(&ofs[ei[(size_t)E + e]], 1);
        esrc[pos] = ei[e];
    }
}

// ---------------------------------------------------------------------------
// warp per node: inv L2 norm; write normalized fp16 row + row norm (hscale).
template <int VPT>
__global__ void normfn_kernel(const float* __restrict__ h, __half* __restrict__ fn,
                              float* __restrict__ hscale, int n, int d4) {
    int node = (blockIdx.x * blockDim.x + threadIdx.x) >> 5;
    int lane = threadIdx.x & 31;
    if (node >= n) return;
    const float4* row = (const float4*)h + (size_t)node * d4;
    float4 c[VPT];
    float acc = 0.f;
    #pragma unroll
    for (int v = 0; v < VPT; v++) {
        int j = lane + v * 32;
        if (j < d4) {
            float4 t = row[j];
            c[v] = t;
            acc += t.x * t.x + t.y * t.y + t.z * t.z + t.w * t.w;
        }
    }
    #pragma unroll
    for (int o = 16; o; o >>= 1) acc += __shfl_xor_sync(0xffffffffu, acc, o);
    float iv = (acc == 0.f) ? 1.f : rsqrtf(acc);
    if (lane == 0) hscale[node] = (acc == 0.f) ? 1.f : sqrtf(acc);
    uint2* frow = (uint2*)(fn + (size_t)node * (d4 * 4));
    #pragma unroll
    for (int v = 0; v < VPT; v++) {
        int j = lane + v * 32;
        if (j < d4) {
            __half2 lo = __floats2half2_rn(c[v].x * iv, c[v].y * iv);
            __half2 hi = __floats2half2_rn(c[v].z * iv, c[v].w * iv);
            uint2 u;
            u.x = *(unsigned*)&lo;
            u.y = *(unsigned*)&hi;
            frow[j] = u;
        }
    }
}

// warp per dst node: fp16 dot vs cached dst row; w in CSR order; rowsum atomics
template <int VPT>
__global__ void sim_csr_kernel(const __half* __restrict__ fn,
                               const int* __restrict__ rowptr,
                               const int* __restrict__ esrc,
                               float* __restrict__ w, float* __restrict__ rowsum,
                               int n, int d4) {
    int node = (int)(((size_t)blockIdx.x * blockDim.x + threadIdx.x) >> 5);
    int lane = threadIdx.x & 31;
    if (node >= n) return;
    const uint2* f2 = (const uint2*)fn;
    const uint2* ft = f2 + (size_t)node * d4;
    float4 cached[VPT];
    #pragma unroll
    for (int v = 0; v < VPT; v++) {
        int j = lane + v * 32;
        if (j < d4) {
            uint2 u = ft[j];
            float2 lo = __half22float2(*(__half2*)&u.x);
            float2 hi = __half22float2(*(__half2*)&u.y);
            cached[v] = make_float4(lo.x, lo.y, hi.x, hi.y);
        } else cached[v] = make_float4(0.f, 0.f, 0.f, 0.f);
    }
    int p0 = rowptr[node], p1 = rowptr[node + 1];
    for (int p = p0; p < p1; p++) {
        int s = esrc[p];
        const uint2* fs = f2 + (size_t)s * d4;
        float acc = 0.f;
        #pragma unroll
        for (int v = 0; v < VPT; v++) {
            int j = lane + v * 32;
            if (j < d4) {
                uint2 u = fs[j];
                float2 lo = __half22float2(*(__half2*)&u.x);
                float2 hi = __half22float2(*(__half2*)&u.y);
                float4 b = cached[v];
                acc += lo.x * b.x + lo.y * b.y + hi.x * b.z + hi.y * b.w;
            }
        }
        #pragma unroll
        for (int o = 16; o; o >>= 1) acc += __shfl_xor_sync(0xffffffffu, acc, o);
        if (lane == 0) {
            float wv = (s != node && acc >= 0.f) ? acc : 0.f;
            w[p] = wv;
            if (wv > 0.f) atomicAdd(&rowsum[s], wv);
        }
    }
}

__global__ void edge2_csr_kernel(const int* __restrict__ rowptr,
                                 const int* __restrict__ esrc,
                                 float* __restrict__ w,
                                 const float* __restrict__ rowsum,
                                 float* __restrict__ deg, float* __restrict__ degG,
                                 int n) {
    int t = blockIdx.x * blockDim.x + threadIdx.x;
    if (t >= n) return;
    int p0 = rowptr[t], p1 = rowptr[t + 1];
    float dsum = 0.f;
    for (int p = p0; p < p1; p++) {
        float wv = w[p];
        if (wv > 0.f) {
            int s = esrc[p];
            float ew = expf(wv / rowsum[s]);
            atomicAdd(&deg[s], 1.0f);
            dsum += ew;
            w[p] = ew;
        }
    }
    degG[t] = dsum;
}

__global__ void node2_kernel(const float* __restrict__ deg,
                             const float* __restrict__ degG,
                             float* __restrict__ sw, float* __restrict__ dinv,
                             int n) {
    int i = blockIdx.x * blockDim.x + threadIdx.x;
    if (i >= n) return;
    float s = expf(1.0f / (deg[i] + 1.0f));
    sw[i] = s;
    dinv[i] = rsqrtf(degG[i] + s);
}

// ---------------------------------------------------------------------------
// W (fp32) -> fp16
__global__ void convw_kernel(const float* __restrict__ W, __half* __restrict__ Wh, int total) {
    int i = blockIdx.x * blockDim.x + threadIdx.x;
    if (i < total) Wh[i] = __float2half(W[i]);
}

// HMMA GEMM v2: C[n_pad x m] = A(fp16) @ Wh, fp32 accum.
// 256 threads = 8 warps (4 row x 2 col). Tile 128 rows x m cols.
// Each warp: 2 row-frags x FC col-frags. m == 32*FC. Padded smem pitches.
#define AP 24          // As pitch in halves (16 data + 8 pad)
template <int FC>
__global__ void __launch_bounds__(256) hmma2_kernel(
        const __half* __restrict__ A, const __half* __restrict__ Wh,
        float* __restrict__ C, int k, int m) {
    __shared__ __align__(16) __half As[128 * AP];
    __shared__ __align__(16) __half Ws[16 * (32 * FC + 8)];
    const int WP = 32 * FC + 8;    // Ws pitch in halves
    int bm = blockIdx.x * 128;
    int tid = threadIdx.x;
    int wid = tid >> 5;
    int wr = wid >> 1, wc = wid & 1;
    wmma::fragment<wmma::accumulator, 16, 16, 16, float> acc[2][FC];
    #pragma unroll
    for (int i = 0; i < 2; i++)
        #pragma unroll
        for (int f = 0; f < FC; f++) wmma::fill_fragment(acc[i][f], 0.f);
    int mdiv8 = m >> 3;
    for (int k0 = 0; k0 < k; k0 += 16) {
        {   // As: 128 rows x 16 halves; 256 chunks of 16B; 1 per thread
            int r = tid >> 1, seg = (tid & 1) * 8;
            *(float4*)&As[r * AP + seg] =
                *(const float4*)&A[(size_t)(bm + r) * k + k0 + seg];
        }
        // Ws: 16 rows x m halves = 2m chunks of 16B
        for (int f = tid; f < 2 * m; f += 256) {
            int r = f / mdiv8, c = (f % mdiv8) * 8;
            *(float4*)&Ws[r * WP + c] = *(const float4*)&Wh[(size_t)(k0 + r) * m + c];
        }
        __syncthreads();
        wmma::fragment<wmma::matrix_a, 16, 16, 16, __half, wmma::row_major> fa0, fa1;
        wmma::load_matrix_sync(fa0, &As[(wr * 32) * AP], AP);
        wmma::load_matrix_sync(fa1, &As[(wr * 32 + 16) * AP], AP);
        #pragma unroll
        for (int f = 0; f < FC; f++) {
            wmma::fragment<wmma::matrix_b, 16, 16, 16, __half, wmma::row_major> fb;
            wmma::load_matrix_sync(fb, &Ws[(wc * FC + f) * 16], WP);
            wmma::mma_sync(acc[0][f], fa0, fb, acc[0][f]);
            wmma::mma_sync(acc[1][f], fa1, fb, acc[1][f]);
        }
        __syncthreads();
    }
    #pragma unroll
    for (int i = 0; i < 2; i++)
        #pragma unroll
        for (int f = 0; f < FC; f++)
            wmma::store_matrix_sync(
                &C[(size_t)(bm + wr * 32 + i * 16) * m + (wc * FC + f) * 16],
                acc[i][f], m, wmma::mem_row_major);
}

// ---------------------------------------------------------------------------
// SIMT GEMM (layer 3): 128x64 tile, 8x4 micro (general m, k % 16 == 0)
__global__ void __launch_bounds__(256) gemm64_kernel(
        const float* __restrict__ A, const float* __restrict__ W,
        float* __restrict__ C, int n, int k, int m) {
    __shared__ float As[16][128];
    __shared__ float Ws[16][64];
    int bm = blockIdx.y * 128;
    int bn = blockIdx.x * 64;
    int tid = threadIdx.x;
    int tr = tid >> 4, tc = tid & 15;
    float acc[8][4] = {};
    for (int k0 = 0; k0 < k; k0 += 16) {
        #pragma unroll
        for (int l = 0; l < 2; l++) {
            int f = tid * 2 + l;
            int r = f >> 2;
            int c4 = (f & 3) * 4;
            int gr = bm + r;
            float4 v = make_float4(0.f, 0.f, 0.f, 0.f);
            if (gr < n) v = *(const float4*)&A[(size_t)gr * k + k0 + c4];
            As[c4 + 0][r] = v.x; As[c4 + 1][r] = v.y;
            As[c4 + 2][r] = v.z; As[c4 + 3][r] = v.w;
        }
        {
            int r = tid >> 4;
            int c4 = (tid & 15) * 4;
            int gc = bn + c4;
            const float* wrow = &W[(size_t)(k0 + r) * m];
            float4 v;
            if (gc + 3 < m) v = *(const float4*)&wrow[gc];
            else {
                v.x = (gc + 0 < m) ? wrow[gc + 0] : 0.f;
                v.y = (gc + 1 < m) ? wrow[gc + 1] : 0.f;
                v.z = (gc + 2 < m) ? wrow[gc + 2] : 0.f;
                v.w = (gc + 3 < m) ? wrow[gc + 3] : 0.f;
            }
            *(float4*)&Ws[r][c4] = v;
        }
        __syncthreads();
        #pragma unroll
        for (int kk = 0; kk < 16; kk++) {
            float a[8];
            *(float4*)&a[0] = *(float4*)&As[kk][tr * 8];
            *(float4*)&a[4] = *(float4*)&As[kk][tr * 8 + 4];
            float4 wv = *(float4*)&Ws[kk][tc * 4];
            #pragma unroll
            for (int i = 0; i < 8; i++) {
                acc[i][0] += a[i] * wv.x;
                acc[i][1] += a[i] * wv.y;
                acc[i][2] += a[i] * wv.z;
                acc[i][3] += a[i] * wv.w;
            }
        }
        __syncthreads();
    }
    #pragma unroll
    for (int i = 0; i < 8; i++) {
        int gr = bm + tr * 8 + i;
        if (gr >= n) continue;
        int gc = bn + tc * 4;
        if (gc + 3 < m) {
            *(float4*)&C[(size_t)gr * m + gc] =
                make_float4(acc[i][0], acc[i][1], acc[i][2], acc[i][3]);
        } else {
            #pragma unroll
            for (int j = 0; j < 4; j++)
                if (gc + j < m) C[(size_t)gr * m + gc + j] = acc[i][j];
        }
    }
}

// ---------------------------------------------------------------------------
// CSR aggregation: fused self-loop + bias + optional relu + per-row hscale.
template <int VPT>
__global__ void agg_csr_kernel(const int* __restrict__ rowptr,
                               const int* __restrict__ esrc,
                               const float* __restrict__ w,
                               const float* __restrict__ dinv,
                               const float* __restrict__ sw,
                               const float* __restrict__ hw,
                               const float* __restrict__ b,
                               const float* __restrict__ hscale,
                               float* __restrict__ out,
                               int n, int m4, int relu) {
    int node = (int)(((size_t)blockIdx.x * blockDim.x + threadIdx.x) >> 5);
    int lane = threadIdx.x & 31;
    if (node >= n) return;
    float4 acc[VPT];
    #pragma unroll
    for (int v = 0; v < VPT; v++) acc[v] = make_float4(0.f, 0.f, 0.f, 0.f);
    float dt = dinv[node];
    int p0 = rowptr[node], p1 = rowptr[node + 1];
    const float4* hw4 = (const float4*)hw;
    for (int p = p0; p < p1; p++) {
        float ew = w[p];
        if (ew == 0.f) continue;
        int s = esrc[p];
        float sc = hscale ? hscale[s] : 1.f;
        float coef = ew * dinv[s] * dt * sc;
        const float4* row = hw4 + (size_t)s * m4;
        #pragma unroll
        for (int v = 0; v < VPT; v++) {
            int j = lane + v * 32;
            if (j < m4) {
                float4 hv = row[j];
                acc[v].x += coef * hv.x; acc[v].y += coef * hv.y;
                acc[v].z += coef * hv.z; acc[v].w += coef * hv.w;
            }
        }
    }
    float selfsc = hscale ? hscale[node] : 1.f;
    float self = sw[node] * dt * dt * selfsc;
    const float4* srow = hw4 + (size_t)node * m4;
    float4* orow = (float4*)out + (size_t)node * m4;
    const float4* b4 = (const float4*)b;
    #pragma unroll
    for (int v = 0; v < VPT; v++) {
        int j = lane + v * 32;
        if (j < m4) {
            float4 hv = srow[j];
            float4 bv = b4[j];
            float4 r;
            r.x = acc[v].x + self * hv.x + bv.x;
            r.y = acc[v].y + self * hv.y + bv.y;
            r.z = acc[v].z + self * hv.z + bv.z;
            r.w = acc[v].w + self * hv.w + bv.w;
            if (relu) {
                r.x = fmaxf(r.x, 0.f); r.y = fmaxf(r.y, 0.f);
                r.z = fmaxf(r.z, 0.f); r.w = fmaxf(r.w, 0.f);
            }
            orow[j] = r;
        }
    }
}

// warp per row log_softmax
__global__ void lsm_kernel(float* __restrict__ out, int n, int m) {
    int row = (blockIdx.x * blockDim.x + threadIdx.x) >> 5;
    int lane = threadIdx.x & 31;
    if (row >= n) return;
    float* r = out + (size_t)row * m;
    float mx = -1e30f;
    for (int j = lane; j < m; j += 32) mx = fmaxf(mx, r[j]);
    #pragma unroll
    for (int o = 16; o; o >>= 1) mx = fmaxf(mx, __shfl_xor_sync(0xffffffffu, mx, o));
    float se = 0.f;
    for (int j = lane; j < m; j += 32) se += expf(r[j] - mx);
    #pragma unroll
    for (int o = 16; o; o >>= 1) se += __shfl_xor_sync(0xffffffffu, se, o);
    float l = mx + logf(se);
    for (int j = lane; j < m; j += 32) r[j] -= l;
}

// ---------------------------------------------------------------------------
static void run_layer(const float* h, int d, const float* W, const float* b,
                      int dout, int n,
                      float* hw, float* rowsum, float* deg, float* degG,
                      __half* fn, __half* wh, float* hscale,
                      float* w, float* sw, float* dinv,
                      const int* rowptr, const int* esrc,
                      float* out, bool do_relu, bool use_hmma) {
    const int T = 256;
    int d4 = d >> 2;
    clear2_kernel<<<(n + T - 1) / T, T>>>(rowsum, deg, n);
    int wb = (int)(((size_t)n * 32 + T - 1) / T);
    if (d4 > 64)       normfn_kernel<4><<<wb, T>>>(h, fn, hscale, n, d4);
    else if (d4 > 32)  normfn_kernel<2><<<wb, T>>>(h, fn, hscale, n, d4);
    else               normfn_kernel<1><<<wb, T>>>(h, fn, hscale, n, d4);
    if (d4 > 64)       sim_csr_kernel<4><<<wb, T>>>(fn, rowptr, esrc, w, rowsum, n, d4);
    else if (d4 > 32)  sim_csr_kernel<2><<<wb, T>>>(fn, rowptr, esrc, w, rowsum, n, d4);
    else               sim_csr_kernel<1><<<wb, T>>>(fn, rowptr, esrc, w, rowsum, n, d4);
    edge2_csr_kernel<<<(n + T - 1) / T, T>>>(rowptr, esrc, w, rowsum, deg, degG, n);
    node2_kernel<<<(n + T - 1) / T, T>>>(deg, degG, sw, dinv, n);
    const float* agg_hscale = nullptr;
    if (use_hmma) {
        convw_kernel<<<(d * dout + T - 1) / T, T>>>(W, wh, d * dout);
        int gb = (n + 127) / 128;
        if (dout == 256)     hmma2_kernel<8><<<gb, 256>>>(fn, wh, hw, d, dout);
        else                 hmma2_kernel<2><<<gb, 256>>>(fn, wh, hw, d, dout);
        agg_hscale = hscale;
    } else {
        dim3 gg((dout + 63) / 64, (n + 127) / 128);
        gemm64_kernel<<<gg, 256>>>(h, W, hw, n, d, dout);
    }
    int m4 = dout >> 2;
    if (m4 > 32)
        agg_csr_kernel<2><<<wb, T>>>(rowptr, esrc, w, dinv, sw, hw, b, agg_hscale,
                                     out, n, m4, do_relu ? 1 : 0);
    else
        agg_csr_kernel<1><<<wb, T>>>(rowptr, esrc, w, dinv, sw, hw, b, agg_hscale,
                                     out, n, m4, do_relu ? 1 : 0);
}

extern "C" void kernel_launch(void* const* d_in, const int* in_sizes, int n_in,
                              void* d_out, int out_size) {
    const float* x = (const float*)d_in[0];
    const int* ei = (const int*)d_in[1];     // int32 (JAX default)
    const float* W1 = (const float*)d_in[2];
    const float* b1 = (const float*)d_in[3];
    const float* W2 = (const float*)d_in[4];
    const float* b2 = (const float*)d_in[5];
    const float* W3 = (const float*)d_in[6];
    const float* b3 = (const float*)d_in[7];
    float* out = (float*)d_out;

    int H  = in_sizes[3];          // 256
    int D2 = in_sizes[5];          // 64
    int C  = in_sizes[7];          // 40
    int F  = in_sizes[2] / H;      // 512
    int n  = in_sizes[0] / F;      // 50000
    int E  = in_sizes[1] / 2;      // 1600000

    float *p_h1, *p_h2, *p_hw, *p_w, *p_hscale, *p_rowsum, *p_deg, *p_degG, *p_sw, *p_dinv;
    __half *p_fn, *p_wh;
    int *p_rowptr, *p_ofs, *p_esrc, *p_bsum;
    cudaGetSymbolAddress((void**)&p_h1, g_h1);
    cudaGetSymbolAddress((void**)&p_h2, g_h2);
    cudaGetSymbolAddress((void**)&p_hw, g_hw);
    cudaGetSymbolAddress((void**)&p_fn, g_fn);
    cudaGetSymbolAddress((void**)&p_wh, g_wh);
    cudaGetSymbolAddress((void**)&p_w, g_w);
    cudaGetSymbolAddress((void**)&p_hscale, g_hscale);
    cudaGetSymbolAddress((void**)&p_rowsum, g_rowsum);
    cudaGetSymbolAddress((void**)&p_deg, g_deg);
    cudaGetSymbolAddress((void**)&p_degG, g_degG);
    cudaGetSymbolAddress((void**)&p_sw, g_sw);
    cudaGetSymbolAddress((void**)&p_dinv, g_dinv);
    cudaGetSymbolAddress((void**)&p_rowptr, g_rowptr);
    cudaGetSymbolAddress((void**)&p_ofs, g_ofs);
    cudaGetSymbolAddress((void**)&p_esrc, g_esrc);
    cudaGetSymbolAddress((void**)&p_bsum, g_bsum);

    const int T = 256;
    // Zero the padded tail of fn once (so padded wmma A-rows are clean zeros)
    {
        int tail = 128 * 512;
        zeroh_kernel<<<(tail + T - 1) / T, T>>>(p_fn + (size_t)N_MAX * 512, tail);
    }
    // Build CSR by dst once (edge structure identical across layers)
    zeroi_kernel<<<(n + 1 + T - 1) / T, T>>>(p_rowptr, n + 1);
    hist_kernel<<<(E + T - 1) / T, T>>>(ei, p_rowptr, E);
    int nscan = n + 1;
    int nb = (nscan + SCHUNK - 1) / SCHUNK;
    scan1_kernel<<<nb, 1024>>>(p_rowptr, nscan, p_bsum);
    scan2_kernel<<<1, 32>>>(p_bsum, nb);
    if (nb > 1) scan3_kernel<<<nb - 1, 1024>>>(p_rowptr, nscan, p_bsum);
    copyofs_kernel<<<(n + T - 1) / T, T>>>(p_rowptr, p_ofs, n);
    scatter_kernel<<<(E + T - 1) / T, T>>>(ei, p_ofs, p_esrc, E);

    // Layer 1: x(512) -> h1(256), relu, HMMA
    run_layer(x, F, W1, b1, H, n, p_hw, p_rowsum, p_deg, p_degG,
              p_fn, p_wh, p_hscale, p_w, p_sw, p_dinv, p_rowptr, p_esrc,
              p_h1, true, true);
    // Layer 2: h1(256) -> h2(64), relu, HMMA
    run_layer(p_h1, H, W2, b2, D2, n, p_hw, p_rowsum, p_deg, p_degG,
              p_fn, p_wh, p_hscale, p_w, p_sw, p_dinv, p_rowptr, p_esrc,
              p_h2, true, true);
    // Layer 3: h2(64) -> out(40), no relu, SIMT (m=40)
    run_layer(p_h2, D2, W3, b3, C, n, p_hw, p_rowsum, p_deg, p_degG,
              p_fn, p_wh, p_hscale, p_w, p_sw, p_dinv, p_rowptr, p_esrc,
              out, false, false);
    // log_softmax in place on d_out
    lsm_kernel<<<(n * 32 + 255) / 256, 256>>>(out, n, C);
}